// round 2
// baseline (speedup 1.0000x reference)
#include <cuda_runtime.h>
#include <cuda_bf16.h>
#include <math.h>

#define B_ 4096
#define D_ 256
#define NPROTO 256

// ---------------- scratch (device globals; no allocations allowed) ----------------
__device__ float g_h1[B_ * 32 * 15 * 15];   // 29.49M
__device__ float g_h2[B_ * 64 * 8 * 8];     // 16.78M
__device__ float g_h3[B_ * 128 * 8 * 8];    // 33.55M
__device__ float g_h4[B_ * 256 * 8 * 8];    // 67.11M
__device__ float g_z0[B_ * D_];
__device__ float g_z[B_ * D_];
__device__ float g_blend[B_ * D_];
__device__ float g_protosT[NPROTO * D_];
__device__ float g_gridT[NPROTO * D_];
__device__ float g_pn2[NPROTO];
__device__ float g_gn2[NPROTO];
__device__ float g_wsum[D_ * 10];

// ---------------- prep: transpose protos/grid, norms, summed classifier ----------------
__global__ void prep_kernel(const float* __restrict__ protos,
                            const float* __restrict__ grid_pos,
                            const float* __restrict__ clf_w) {
    int bid = blockIdx.x;
    int tid = threadIdx.x;  // 256
    if (bid < NPROTO) {
        float pv = protos[bid * D_ + tid];
        float gv = grid_pos[bid * D_ + tid];
        g_protosT[tid * NPROTO + bid] = pv;
        g_gridT[tid * NPROTO + bid] = gv;
        __shared__ float red[256];
        red[tid] = pv * pv;
        __syncthreads();
        for (int s = 128; s > 0; s >>= 1) { if (tid < s) red[tid] += red[tid + s]; __syncthreads(); }
        if (tid == 0) g_pn2[bid] = red[0];
        __syncthreads();
        red[tid] = gv * gv;
        __syncthreads();
        for (int s = 128; s > 0; s >>= 1) { if (tid < s) red[tid] += red[tid + s]; __syncthreads(); }
        if (tid == 0) g_gn2[bid] = red[0];
    } else {
        // wsum[d][c] = sum_h clf_w[(h*256+d)*10 + c]
        for (int i = tid; i < D_ * 10; i += 256) {
            int dd = i / 10, c = i % 10;
            float s = 0.f;
            #pragma unroll
            for (int h = 0; h < 4; h++) s += clf_w[(h * 256 + dd) * 10 + c];
            g_wsum[i] = s;
        }
    }
}

// ---------------- conv1: 3->32, 5x5, stride 2, pad 1 : (32,15,15) out ----------------
__global__ void conv1_kernel(const float* __restrict__ x,
                             const float* __restrict__ w,
                             const float* __restrict__ bias) {
    __shared__ float xs[3 * 32 * 32];   // 3072
    __shared__ float ws[32 * 3 * 25];   // 2400
    int b = blockIdx.x, tid = threadIdx.x;   // 256 threads
    const float* xb = x + (size_t)b * 3072;
    for (int i = tid; i < 3072; i += 256) xs[i] = xb[i];
    for (int i = tid; i < 2400; i += 256) ws[i] = w[i];
    __syncthreads();
    for (int o = tid; o < 32 * 225; o += 256) {
        int oc = o / 225, pos = o % 225;
        int oh = pos / 15, ow = pos % 15;
        float acc = bias[oc];
        #pragma unroll
        for (int c = 0; c < 3; c++) {
            #pragma unroll
            for (int kh = 0; kh < 5; kh++) {
                int ih = 2 * oh - 1 + kh;
                if ((unsigned)ih < 32u) {
                    #pragma unroll
                    for (int kw = 0; kw < 5; kw++) {
                        int iw = 2 * ow - 1 + kw;
                        if ((unsigned)iw < 32u)
                            acc += xs[(c * 32 + ih) * 32 + iw] * ws[(oc * 3 + c) * 25 + kh * 5 + kw];
                    }
                }
            }
        }
        g_h1[(size_t)b * 7200 + o] = fmaxf(acc, 0.f);
    }
}

// ---------------- conv2: 32->64, 3x3, stride 2, pad 1 : (64,8,8) out ----------------
__global__ void conv2_kernel(const float* __restrict__ w,
                             const float* __restrict__ bias) {
    __shared__ float xs[32 * 225];  // 7200 floats = 28.8KB
    int b = blockIdx.x, tid = threadIdx.x;  // 128 threads
    const float* inb = g_h1 + (size_t)b * 7200;
    for (int i = tid; i < 7200; i += 128) xs[i] = inb[i];
    __syncthreads();
    int row = tid & 7;       // output row 0..7
    int ocg = tid >> 3;      // 0..15 -> oc = ocg*4..+3
    float acc[4][8];
    #pragma unroll
    for (int i = 0; i < 4; i++) {
        float bv = bias[ocg * 4 + i];
        #pragma unroll
        for (int j = 0; j < 8; j++) acc[i][j] = bv;
    }
    for (int c = 0; c < 32; c++) {
        #pragma unroll
        for (int kh = 0; kh < 3; kh++) {
            int ih = 2 * row - 1 + kh;
            if ((unsigned)ih < 15u) {
                float xr[17];
                xr[0] = 0.f; xr[16] = 0.f;
                #pragma unroll
                for (int i = 0; i < 15; i++) xr[i + 1] = xs[c * 225 + ih * 15 + i];
                #pragma unroll
                for (int i2 = 0; i2 < 4; i2++) {
                    int oc = ocg * 4 + i2;
                    const float* wp = w + ((size_t)(oc * 32 + c) * 3 + kh) * 3;
                    float w0 = __ldg(wp), w1 = __ldg(wp + 1), w2 = __ldg(wp + 2);
                    #pragma unroll
                    for (int ow = 0; ow < 8; ow++)
                        acc[i2][ow] += xr[2 * ow] * w0 + xr[2 * ow + 1] * w1 + xr[2 * ow + 2] * w2;
                }
            }
        }
    }
    #pragma unroll
    for (int i2 = 0; i2 < 4; i2++) {
        int oc = ocg * 4 + i2;
        #pragma unroll
        for (int ow = 0; ow < 8; ow++)
            g_h2[(size_t)b * 4096 + oc * 64 + row * 8 + ow] = fmaxf(acc[i2][ow], 0.f);
    }
}

// ---------------- conv 3x3 s1 p1 on 8x8 (templated; conv3 & conv4) ----------------
template <int CIN, int COUT>
__global__ void conv3x3_kernel(const float* __restrict__ in,
                               const float* __restrict__ w,
                               const float* __restrict__ bias,
                               float* __restrict__ out) {
    __shared__ float xs[CIN * 64];
    int b = blockIdx.x, tid = threadIdx.x;   // (COUT/4)*8 threads
    const float* inb = in + (size_t)b * CIN * 64;
    for (int i = tid; i < CIN * 64; i += blockDim.x) xs[i] = inb[i];
    __syncthreads();
    int row = tid & 7;
    int ocg = tid >> 3;
    float acc[4][8];
    #pragma unroll
    for (int i = 0; i < 4; i++) {
        float bv = bias[ocg * 4 + i];
        #pragma unroll
        for (int j = 0; j < 8; j++) acc[i][j] = bv;
    }
    for (int c = 0; c < CIN; c++) {
        #pragma unroll
        for (int kh = 0; kh < 3; kh++) {
            int ih = row - 1 + kh;
            if ((unsigned)ih < 8u) {
                float xr[10];
                xr[0] = 0.f; xr[9] = 0.f;
                #pragma unroll
                for (int i = 0; i < 8; i++) xr[i + 1] = xs[c * 64 + ih * 8 + i];
                #pragma unroll
                for (int i2 = 0; i2 < 4; i2++) {
                    int oc = ocg * 4 + i2;
                    const float* wp = w + ((size_t)(oc * CIN + c) * 3 + kh) * 3;
                    float w0 = __ldg(wp), w1 = __ldg(wp + 1), w2 = __ldg(wp + 2);
                    #pragma unroll
                    for (int ow = 0; ow < 8; ow++)
                        acc[i2][ow] += xr[ow] * w0 + xr[ow + 1] * w1 + xr[ow + 2] * w2;
                }
            }
        }
    }
    float* outb = out + (size_t)b * COUT * 64;
    #pragma unroll
    for (int i2 = 0; i2 < 4; i2++) {
        int oc = ocg * 4 + i2;
        #pragma unroll
        for (int ow = 0; ow < 8; ow++)
            outb[oc * 64 + row * 8 + ow] = fmaxf(acc[i2][ow], 0.f);
    }
}

// ---------------- tiled fp32 GEMM: C[M,N] = A[M,K] @ B[K,N] + bias ----------------
// BM=64, BN=64, BK=8, 256 threads, 4x4 micro-tile
__global__ void gemm_kernel(const float* __restrict__ A, const float* __restrict__ Bm,
                            const float* __restrict__ bias, float* __restrict__ C,
                            int K, int N) {
    __shared__ float As[8][68];
    __shared__ float Bs[8][68];
    int tid = threadIdx.x;
    int row0 = blockIdx.x * 64;
    int col0 = blockIdx.y * 64;
    int tr = tid / 16, tc = tid % 16;
    int ar = tid / 8, ac = tid % 8;     // A: 32 rows x 8 cols per pass, 2 passes
    int br = tid / 64, bc = tid % 64;   // B: 4 rows x 64 cols per pass, 2 passes
    float acc[4][4];
    #pragma unroll
    for (int i = 0; i < 4; i++)
        #pragma unroll
        for (int j = 0; j < 4; j++) acc[i][j] = 0.f;

    for (int k0 = 0; k0 < K; k0 += 8) {
        #pragma unroll
        for (int i = 0; i < 2; i++)
            As[ac][ar + i * 32] = A[(size_t)(row0 + ar + i * 32) * K + k0 + ac];
        #pragma unroll
        for (int i = 0; i < 2; i++)
            Bs[br + i * 4][bc] = Bm[(size_t)(k0 + br + i * 4) * N + col0 + bc];
        __syncthreads();
        #pragma unroll
        for (int kk = 0; kk < 8; kk++) {
            float4 a = *(const float4*)&As[kk][tr * 4];
            float4 b = *(const float4*)&Bs[kk][tc * 4];
            acc[0][0] += a.x * b.x; acc[0][1] += a.x * b.y; acc[0][2] += a.x * b.z; acc[0][3] += a.x * b.w;
            acc[1][0] += a.y * b.x; acc[1][1] += a.y * b.y; acc[1][2] += a.y * b.z; acc[1][3] += a.y * b.w;
            acc[2][0] += a.z * b.x; acc[2][1] += a.z * b.y; acc[2][2] += a.z * b.z; acc[2][3] += a.z * b.w;
            acc[3][0] += a.w * b.x; acc[3][1] += a.w * b.y; acc[3][2] += a.w * b.z; acc[3][3] += a.w * b.w;
        }
        __syncthreads();
    }
    #pragma unroll
    for (int i = 0; i < 4; i++) {
        int r = row0 + tr * 4 + i;
        #pragma unroll
        for (int j = 0; j < 4; j++) {
            int cidx = col0 + tc * 4 + j;
            C[(size_t)r * N + cidx] = acc[i][j] + bias[cidx];
        }
    }
}

// ---------------- proto distances + softmax/gate + blend (8 rows/block) ----------------
__global__ void proto_kernel(const float* __restrict__ protos,
                             const float* __restrict__ temp_raw,
                             const float* __restrict__ gate) {
    __shared__ float zs[8 * 256];
    __shared__ float dsm[8 * 256];
    __shared__ float wsm[8 * 256];
    __shared__ float zn2[8];
    int b0 = blockIdx.x * 8;
    int tid = threadIdx.x;  // 256
    for (int i = tid; i < 2048; i += 256) zs[i] = g_z[(size_t)b0 * 256 + i];
    __syncthreads();
    if (tid < 8) {
        float s = 0.f;
        for (int k = 0; k < 256; k++) { float v = zs[tid * 256 + k]; s += v * v; }
        zn2[tid] = s;
    }
    __syncthreads();
    int j = tid;
    float ap[8], ag[8];
    #pragma unroll
    for (int r = 0; r < 8; r++) { ap[r] = 0.f; ag[r] = 0.f; }
    for (int k = 0; k < 256; k++) {
        float pv = g_protosT[k * 256 + j];
        float gv = g_gridT[k * 256 + j];
        #pragma unroll
        for (int r = 0; r < 8; r++) {
            float zv = zs[r * 256 + k];
            ap[r] += zv * pv;
            ag[r] += zv * gv;
        }
    }
    float pj = g_pn2[j], gj = g_gn2[j];
    #pragma unroll
    for (int r = 0; r < 8; r++) {
        float d1 = sqrtf(fmaxf(zn2[r] + pj - 2.f * ap[r], 0.f));
        float d2 = sqrtf(fmaxf(zn2[r] + gj - 2.f * ag[r], 0.f));
        dsm[r * 256 + j] = d1 + d2;
    }
    __syncthreads();

    float temp = 1.f / (1.f + expf(-temp_raw[0])) * 0.999f + 0.001f;
    float invt = 1.f / temp;
    int wr = tid >> 5;   // warp = row
    int lane = tid & 31;
    // min distance over row
    float mn = dsm[wr * 256 + lane];
    #pragma unroll
    for (int t = 1; t < 8; t++) mn = fminf(mn, dsm[wr * 256 + lane + t * 32]);
    #pragma unroll
    for (int o = 16; o; o >>= 1) mn = fminf(mn, __shfl_xor_sync(0xffffffffu, mn, o));
    float pvals[8];
    float S = 0.f;
    #pragma unroll
    for (int t = 0; t < 8; t++) {
        float e = expf((mn - dsm[wr * 256 + lane + t * 32]) * invt);
        pvals[t] = e; S += e;
    }
    #pragma unroll
    for (int o = 16; o; o >>= 1) S += __shfl_xor_sync(0xffffffffu, S, o);
    float invS = 1.f / S;
    float T = 0.f;
    #pragma unroll
    for (int t = 0; t < 8; t++) {
        int jj = lane + t * 32;
        float sg = 1.f / (1.f + expf(-gate[jj]));
        float bb = pvals[t] * invS * sg;
        pvals[t] = bb; T += bb;
    }
    #pragma unroll
    for (int o = 16; o; o >>= 1) T += __shfl_xor_sync(0xffffffffu, T, o);
    float inv = 1.f / (T + 1e-8f);
    #pragma unroll
    for (int t = 0; t < 8; t++) wsm[wr * 256 + lane + t * 32] = pvals[t] * inv;
    __syncthreads();

    // blended = w @ protos
    int d = tid;
    float accb[8];
    #pragma unroll
    for (int r = 0; r < 8; r++) accb[r] = 0.f;
    for (int jj = 0; jj < 256; jj++) {
        float pv = protos[(size_t)jj * 256 + d];
        #pragma unroll
        for (int r = 0; r < 8; r++) accb[r] += wsm[r * 256 + jj] * pv;
    }
    #pragma unroll
    for (int r = 0; r < 8; r++) g_blend[(size_t)(b0 + r) * 256 + d] = accb[r];
}

// ---------------- logits: blended @ wsum + clf_b (attention collapses; n=1) --------
__global__ void logits_kernel(const float* __restrict__ clf_b, float* __restrict__ out) {
    __shared__ float bs[32 * 256];   // 32KB
    __shared__ float ws[2560];       // 10KB
    int b0 = blockIdx.x * 32;
    int tid = threadIdx.x;  // 320
    for (int i = tid; i < 8192; i += 320) bs[i] = g_blend[(size_t)b0 * 256 + i];
    for (int i = tid; i < 2560; i += 320) ws[i] = g_wsum[i];
    __syncthreads();
    int r = tid / 10, c = tid % 10;
    float acc = clf_b[c];
    for (int d = 0; d < 256; d++) acc += bs[r * 256 + d] * ws[d * 10 + c];
    out[(size_t)(b0 + r) * 10 + c] = acc;
}

// ---------------- launch ----------------
extern "C" void kernel_launch(void* const* d_in, const int* in_sizes, int n_in,
                              void* d_out, int out_size) {
    const float* x        = (const float*)d_in[0];
    // d_in[1] = y (int32) : unused (attention over 1 node is identity)
    const float* conv1_w  = (const float*)d_in[2];
    const float* conv1_b  = (const float*)d_in[3];
    const float* conv2_w  = (const float*)d_in[4];
    const float* conv2_b  = (const float*)d_in[5];
    const float* conv3_w  = (const float*)d_in[6];
    const float* conv3_b  = (const float*)d_in[7];
    const float* conv4_w  = (const float*)d_in[8];
    const float* conv4_b  = (const float*)d_in[9];
    const float* enc_w    = (const float*)d_in[10];
    const float* enc_b    = (const float*)d_in[11];
    // 12 class_emb, 13 node_emb, 14 query_w, 15 query_b, 16 attn_w, 17 attn_b : dead code
    const float* clf_w    = (const float*)d_in[18];
    const float* clf_b    = (const float*)d_in[19];
    const float* node_fc_w = (const float*)d_in[20];
    const float* node_fc_b = (const float*)d_in[21];
    const float* protos   = (const float*)d_in[22];
    const float* grid_pos = (const float*)d_in[23];
    const float* temp_raw = (const float*)d_in[24];
    const float* gate     = (const float*)d_in[25];
    float* out = (float*)d_out;

    float *p_h2, *p_h3, *p_h4, *p_z0, *p_z;
    cudaGetSymbolAddress((void**)&p_h2, g_h2);
    cudaGetSymbolAddress((void**)&p_h3, g_h3);
    cudaGetSymbolAddress((void**)&p_h4, g_h4);
    cudaGetSymbolAddress((void**)&p_z0, g_z0);
    cudaGetSymbolAddress((void**)&p_z, g_z);

    prep_kernel<<<257, 256>>>(protos, grid_pos, clf_w);
    conv1_kernel<<<B_, 256>>>(x, conv1_w, conv1_b);
    conv2_kernel<<<B_, 128>>>(conv2_w, conv2_b);
    conv3x3_kernel<64, 128><<<B_, 256>>>(p_h2, conv3_w, conv3_b, p_h3);
    conv3x3_kernel<128, 256><<<B_, 512>>>(p_h3, conv4_w, conv4_b, p_h4);

    dim3 g_enc(B_ / 64, D_ / 64);
    gemm_kernel<<<g_enc, 256>>>(p_h4, enc_w, enc_b, p_z0, 16384, D_);
    gemm_kernel<<<g_enc, 256>>>(p_z0, node_fc_w, node_fc_b, p_z, D_, D_);

    proto_kernel<<<B_ / 8, 256>>>(protos, temp_raw, gate);
    logits_kernel<<<B_ / 32, 320>>>(clf_b, out);
}

// round 6
// speedup vs baseline: 3.5093x; 3.5093x over previous
#include <cuda_runtime.h>
#include <cuda_bf16.h>
#include <math.h>
#include <cstdint>

#define B_ 4096
#define D_ 256
#define NPROTO 256

// ---------------- scratch (device globals; no allocations allowed) ----------------
__device__ float g_h1[B_ * 32 * 15 * 15];
__device__ float g_h2[B_ * 64 * 64];      // NHWC [b][px][64]   (tf32-rounded)
__device__ float g_h3[B_ * 64 * 128];     // NHWC [b][px][128]  (tf32-rounded)
__device__ float g_h4[B_ * 64 * 256];     // NHWC [b][px][256]  (tf32-rounded)
__device__ float g_z0[B_ * D_];
__device__ float g_z[B_ * D_];
__device__ float g_blend[B_ * D_];
__device__ float g_protosT[NPROTO * D_];
__device__ float g_gridT[NPROTO * D_];
__device__ float g_pn2[NPROTO];
__device__ float g_gn2[NPROTO];
__device__ float g_wsum[D_ * 10];
__device__ float g_encwT[(size_t)D_ * 16384];    // [d][k] tf32-rounded, k = p*256+c
__device__ float g_w3t[9 * 128 * 64];            // [tap][oc][c] tf32-rounded
__device__ float g_w4t[9 * 256 * 128];

// ================= helpers =================
__device__ __forceinline__ uint32_t smem_u32(const void* p) {
    uint32_t a;
    asm("{ .reg .u64 t; cvta.to.shared.u64 t, %1; cvt.u32.u64 %0, t; }" : "=r"(a) : "l"(p));
    return a;
}
__device__ __forceinline__ uint32_t f2tf32(float f) {
    uint32_t r; asm("cvt.rna.tf32.f32 %0, %1;" : "=r"(r) : "f"(f)); return r;
}
__device__ __forceinline__ void cp16(uint32_t s, const void* g) {
    asm volatile("cp.async.cg.shared.global [%0], [%1], 16;" :: "r"(s), "l"(g));
}
#define CP_COMMIT() asm volatile("cp.async.commit_group;" ::: "memory")
#define CP_WAIT1()  asm volatile("cp.async.wait_group 1;" ::: "memory")

__device__ __forceinline__ void mma8(float c[4], const uint32_t a[4], const uint32_t b[2]) {
    asm volatile(
        "mma.sync.aligned.m16n8k8.row.col.f32.tf32.tf32.f32 "
        "{%0,%1,%2,%3}, {%4,%5,%6,%7}, {%8,%9}, {%0,%1,%2,%3};"
        : "+f"(c[0]), "+f"(c[1]), "+f"(c[2]), "+f"(c[3])
        : "r"(a[0]), "r"(a[1]), "r"(a[2]), "r"(a[3]), "r"(b[0]), "r"(b[1]));
}

// ================= prep kernels =================
__global__ void prep_kernel(const float* __restrict__ protos,
                            const float* __restrict__ grid_pos,
                            const float* __restrict__ clf_w) {
    int bid = blockIdx.x;
    int tid = threadIdx.x;
    if (bid < NPROTO) {
        float pv = protos[bid * D_ + tid];
        float gv = grid_pos[bid * D_ + tid];
        g_protosT[tid * NPROTO + bid] = pv;
        g_gridT[tid * NPROTO + bid] = gv;
        __shared__ float red[256];
        red[tid] = pv * pv;
        __syncthreads();
        for (int s = 128; s > 0; s >>= 1) { if (tid < s) red[tid] += red[tid + s]; __syncthreads(); }
        if (tid == 0) g_pn2[bid] = red[0];
        __syncthreads();
        red[tid] = gv * gv;
        __syncthreads();
        for (int s = 128; s > 0; s >>= 1) { if (tid < s) red[tid] += red[tid + s]; __syncthreads(); }
        if (tid == 0) g_gn2[bid] = red[0];
    } else {
        for (int i = tid; i < D_ * 10; i += 256) {
            int dd = i / 10, c = i % 10;
            float s = 0.f;
            #pragma unroll
            for (int h = 0; h < 4; h++) s += clf_w[(h * 256 + dd) * 10 + c];
            g_wsum[i] = s;
        }
    }
}

// encwT[d][k] = tf32(enc_w[(c*64+p)*256 + d]), k = p*256+c
__global__ void prep_encw(const float* __restrict__ enc_w) {
    __shared__ float s[32][257];
    int k0 = blockIdx.x * 32;
    int tid = threadIdx.x;
    for (int r = 0; r < 32; r++) {
        int k = k0 + r;
        int c = k & 255, p = k >> 8;
        s[r][tid] = enc_w[(size_t)(c * 64 + p) * 256 + tid];
    }
    __syncthreads();
    int lane = tid & 31, w = tid >> 5;
    for (int d = w; d < 256; d += 8)
        g_encwT[(size_t)d * 16384 + k0 + lane] = __uint_as_float(f2tf32(s[lane][d]));
}

// wt[((t*COUT+oc)*CIN)+c] = tf32(w[(oc*CIN+c)*9 + t])
__global__ void prep_wc(const float* __restrict__ w, float* __restrict__ wt, int COUT, int CIN) {
    int i = blockIdx.x * 256 + threadIdx.x;
    if (i >= 9 * COUT * CIN) return;
    int c = i % CIN;
    int oc = (i / CIN) % COUT;
    int t = i / (CIN * COUT);
    wt[i] = __uint_as_float(f2tf32(w[((size_t)(oc * CIN + c)) * 9 + t]));
}

// ================= conv1: 3->32, 5x5, s2, p1 (fp32) =================
__global__ void conv1_kernel(const float* __restrict__ x,
                             const float* __restrict__ w,
                             const float* __restrict__ bias) {
    __shared__ float xs[3 * 32 * 32];
    __shared__ float ws[32 * 3 * 25];
    int b = blockIdx.x, tid = threadIdx.x;
    const float* xb = x + (size_t)b * 3072;
    for (int i = tid; i < 3072; i += 256) xs[i] = xb[i];
    for (int i = tid; i < 2400; i += 256) ws[i] = w[i];
    __syncthreads();
    for (int o = tid; o < 32 * 225; o += 256) {
        int oc = o / 225, pos = o % 225;
        int oh = pos / 15, ow = pos % 15;
        float acc = bias[oc];
        #pragma unroll
        for (int c = 0; c < 3; c++)
            #pragma unroll
            for (int kh = 0; kh < 5; kh++) {
                int ih = 2 * oh - 1 + kh;
                if ((unsigned)ih < 32u) {
                    #pragma unroll
                    for (int kw = 0; kw < 5; kw++) {
                        int iw = 2 * ow - 1 + kw;
                        if ((unsigned)iw < 32u)
                            acc += xs[(c * 32 + ih) * 32 + iw] * ws[(oc * 3 + c) * 25 + kh * 5 + kw];
                    }
                }
            }
        g_h1[(size_t)b * 7200 + o] = fmaxf(acc, 0.f);
    }
}

// ================= conv2: 32->64, 3x3, s2, p1 -> NHWC (tf32-rounded) =================
__global__ void conv2_kernel(const float* __restrict__ w,
                             const float* __restrict__ bias) {
    __shared__ float xs[32 * 225];
    int b = blockIdx.x, tid = threadIdx.x;  // 128
    const float* inb = g_h1 + (size_t)b * 7200;
    for (int i = tid; i < 7200; i += 128) xs[i] = inb[i];
    __syncthreads();
    int row = tid & 7;
    int ocg = tid >> 3;
    float acc[4][8];
    #pragma unroll
    for (int i = 0; i < 4; i++) {
        float bv = bias[ocg * 4 + i];
        #pragma unroll
        for (int j = 0; j < 8; j++) acc[i][j] = bv;
    }
    for (int c = 0; c < 32; c++) {
        #pragma unroll
        for (int kh = 0; kh < 3; kh++) {
            int ih = 2 * row - 1 + kh;
            if ((unsigned)ih < 15u) {
                float xr[17];
                xr[0] = 0.f; xr[16] = 0.f;
                #pragma unroll
                for (int i = 0; i < 15; i++) xr[i + 1] = xs[c * 225 + ih * 15 + i];
                #pragma unroll
                for (int i2 = 0; i2 < 4; i2++) {
                    int oc = ocg * 4 + i2;
                    const float* wp = w + ((size_t)(oc * 32 + c) * 3 + kh) * 3;
                    float w0 = __ldg(wp), w1 = __ldg(wp + 1), w2 = __ldg(wp + 2);
                    #pragma unroll
                    for (int ow = 0; ow < 8; ow++)
                        acc[i2][ow] += xr[2 * ow] * w0 + xr[2 * ow + 1] * w1 + xr[2 * ow + 2] * w2;
                }
            }
        }
    }
    #pragma unroll
    for (int i2 = 0; i2 < 4; i2++) {
        int oc = ocg * 4 + i2;
        #pragma unroll
        for (int ow = 0; ow < 8; ow++)
            g_h2[((size_t)b * 64 + row * 8 + ow) * 64 + oc] =
                __uint_as_float(f2tf32(fmaxf(acc[i2][ow], 0.f)));
    }
}

// ================= mma.sync implicit-GEMM conv 3x3 s1 p1 (NHWC, tf32) =================
// CTA: 2 images, M=128, N=COUT. A frags direct from padded raw-image smem with
// per-tap offsets; B (weights) streamed via 3-deep cp.async ring, one sync/chunk.
template <int CIN, int COUT>
__global__ __launch_bounds__(256, 1) void conv_mma(const float* __restrict__ in,
                                                   const float* __restrict__ wt,
                                                   const float* __restrict__ bias,
                                                   float* __restrict__ out) {
    constexpr int CINP = CIN + 4;
    constexpr int CB = CIN / 32, NCH = 9 * CB;
    constexpr int NW = COUT / 4;   // warp n-tile width
    constexpr int NT = NW / 8;     // n8 tiles per warp
    extern __shared__ float sm[];
    float* RAW = sm;                       // 128 * CINP
    float* BS = sm + 128 * CINP;           // 3 * COUT * 36
    uint32_t rawb = smem_u32(RAW), bsb = smem_u32(BS);

    int tid = threadIdx.x, lane = tid & 31, wid = tid >> 5;
    int mwarp = wid & 1, nwarp = wid >> 1;
    int b0 = blockIdx.x * 2;

    // stage raw input (already tf32-rounded by producer)
    const float* inb = in + (size_t)b0 * 64 * CIN;
    #pragma unroll
    for (int u = 0; u < 128 * CIN / 4 / 256; u++) {
        int i = u * 256 + tid;
        int px = i / (CIN / 4), c4 = i % (CIN / 4);
        cp16(rawb + (uint32_t)(px * CINP + c4 * 4) * 4, inb + (size_t)px * CIN + c4 * 4);
    }
    auto issueB = [&](int j) {
        int cb = j % CB, t = j / CB;
        const float* wb = wt + ((size_t)t * COUT) * CIN + cb * 32;
        uint32_t dst = bsb + (uint32_t)((j % 3) * COUT * 36) * 4;
        #pragma unroll
        for (int u = 0; u < COUT * 8 / 256; u++) {
            int i = u * 256 + tid;
            int oc = i >> 3, c4 = i & 7;
            cp16(dst + (uint32_t)(oc * 36 + c4 * 4) * 4, wb + (size_t)oc * CIN + c4 * 4);
        }
    };
    issueB(0); CP_COMMIT();
    issueB(1); CP_COMMIT();

    float acc[4][NT][4];
    #pragma unroll
    for (int mt = 0; mt < 4; mt++)
        #pragma unroll
        for (int nt = 0; nt < NT; nt++)
            #pragma unroll
            for (int q = 0; q < 4; q++) acc[mt][nt][q] = 0.f;

    for (int i = 0; i < NCH; i++) {
        CP_WAIT1();
        __syncthreads();
        if (i + 2 < NCH) issueB(i + 2);
        CP_COMMIT();
        int cb = i % CB, t = i / CB, kh = t / 3, kw = t % 3;
        int aoff[4][2]; bool am[4][2];
        #pragma unroll
        for (int mt = 0; mt < 4; mt++)
            #pragma unroll
            for (int h = 0; h < 2; h++) {
                int r = mwarp * 64 + mt * 16 + (lane >> 2) + h * 8;
                int img = r >> 6, px = r & 63;
                int ih = (px >> 3) + kh - 1, iw = (px & 7) + kw - 1;
                am[mt][h] = ((unsigned)ih < 8u) && ((unsigned)iw < 8u);
                aoff[mt][h] = ((img << 6) + (ih << 3) + iw) * CINP + cb * 32;
            }
        const float* bsc = BS + (i % 3) * (COUT * 36);
        #pragma unroll
        for (int kk = 0; kk < 4; kk++) {
            int c0 = kk * 8 + (lane & 3);
            uint32_t a[4][4];
            #pragma unroll
            for (int mt = 0; mt < 4; mt++) {
                a[mt][0] = am[mt][0] ? __float_as_uint(RAW[aoff[mt][0] + c0]) : 0u;
                a[mt][1] = am[mt][1] ? __float_as_uint(RAW[aoff[mt][1] + c0]) : 0u;
                a[mt][2] = am[mt][0] ? __float_as_uint(RAW[aoff[mt][0] + c0 + 4]) : 0u;
                a[mt][3] = am[mt][1] ? __float_as_uint(RAW[aoff[mt][1] + c0 + 4]) : 0u;
            }
            uint32_t b[NT][2];
            #pragma unroll
            for (int nt = 0; nt < NT; nt++) {
                int n = nwarp * NW + nt * 8 + (lane >> 2);
                b[nt][0] = __float_as_uint(bsc[n * 36 + c0]);
                b[nt][1] = __float_as_uint(bsc[n * 36 + c0 + 4]);
            }
            #pragma unroll
            for (int mt = 0; mt < 4; mt++)
                #pragma unroll
                for (int nt = 0; nt < NT; nt++)
                    mma8(acc[mt][nt], a[mt], b[nt]);
        }
    }
    // epilogue: bias + relu + tf32-round, NHWC float2 stores
    #pragma unroll
    for (int mt = 0; mt < 4; mt++)
        #pragma unroll
        for (int nt = 0; nt < NT; nt++) {
            int n = nwarp * NW + nt * 8 + (lane & 3) * 2;
            float bv0 = bias[n], bv1 = bias[n + 1];
            #pragma unroll
            for (int h = 0; h < 2; h++) {
                int r = mwarp * 64 + mt * 16 + (lane >> 2) + h * 8;
                int img = r >> 6, px = r & 63;
                float v0 = fmaxf(acc[mt][nt][h * 2 + 0] + bv0, 0.f);
                float v1 = fmaxf(acc[mt][nt][h * 2 + 1] + bv1, 0.f);
                float2 o;
                o.x = __uint_as_float(f2tf32(v0));
                o.y = __uint_as_float(f2tf32(v1));
                *(float2*)(out + ((size_t)(b0 + img) * 64 + px) * COUT + n) = o;
            }
        }
}

// ================= mma.sync GEMM: z0[4096,256] = h4[4096,16384] @ encwT[256,16384]^T =================
// M-tile 128, N-tile 64, K chunks of 32 via 3-deep cp.async ring.
__global__ __launch_bounds__(256, 1) void enc_mma(const float* __restrict__ A,
                                                  const float* __restrict__ Bw,
                                                  const float* __restrict__ bias,
                                                  float* __restrict__ C) {
    constexpr int K = 16384, NCH = K / 32;
    extern __shared__ float sm[];
    float* AS = sm;                  // 3 * 128*36
    float* BSm = sm + 3 * 128 * 36;  // 3 * 64*36
    uint32_t asb = smem_u32(AS), bsb = smem_u32(BSm);
    int tid = threadIdx.x, lane = tid & 31, wid = tid >> 5;
    int mwarp = wid & 1, nwarp = wid >> 1;
    int m0 = blockIdx.x * 128, n0 = blockIdx.y * 64;

    auto issue = [&](int j) {
        int buf = j % 3;
        const float* Ab = A + (size_t)m0 * K + j * 32;
        #pragma unroll
        for (int u = 0; u < 4; u++) {
            int i = u * 256 + tid;
            int r = i >> 3, c4 = i & 7;
            cp16(asb + (uint32_t)(buf * 128 * 36 + r * 36 + c4 * 4) * 4, Ab + (size_t)r * K + c4 * 4);
        }
        const float* Bb = Bw + (size_t)n0 * K + j * 32;
        #pragma unroll
        for (int u = 0; u < 2; u++) {
            int i = u * 256 + tid;
            int r = i >> 3, c4 = i & 7;
            cp16(bsb + (uint32_t)(buf * 64 * 36 + r * 36 + c4 * 4) * 4, Bb + (size_t)r * K + c4 * 4);
        }
    };
    issue(0); CP_COMMIT();
    issue(1); CP_COMMIT();

    float acc[4][2][4];
    #pragma unroll
    for (int mt = 0; mt < 4; mt++)
        #pragma unroll
        for (int nt = 0; nt < 2; nt++)
            #pragma unroll
            for (int q = 0; q < 4; q++) acc[mt][nt][q] = 0.f;

    for (int i = 0; i < NCH; i++) {
        CP_WAIT1();
        __syncthreads();
        if (i + 2 < NCH) issue(i + 2);
        CP_COMMIT();
        const float* asc = AS + (i % 3) * (128 * 36);
        const float* bsc = BSm + (i % 3) * (64 * 36);
        #pragma unroll
        for (int kk = 0; kk < 4; kk++) {
            int c0 = kk * 8 + (lane & 3);
            uint32_t a[4][4];
            #pragma unroll
            for (int mt = 0; mt < 4; mt++) {
                int r = mwarp * 64 + mt * 16 + (lane >> 2);
                a[mt][0] = __float_as_uint(asc[r * 36 + c0]);
                a[mt][1] = __float_as_uint(asc[(r + 8) * 36 + c0]);
                a[mt][2] = __float_as_uint(asc[r * 36 + c0 + 4]);
                a[mt][3] = __float_as_uint(asc[(r + 8) * 36 + c0 + 4]);
            }
            uint32_t b[2][2];
            #pragma unroll
            for (int nt = 0; nt < 2; nt++) {
                int n = nwarp * 16 + nt * 8 + (lane >> 2);
                b[nt][0] = __float_as_uint(bsc[n * 36 + c0]);
                b[nt][1] = __float_as_uint(bsc[n * 36 + c0 + 4]);
            }
            #pragma unroll
            for (int mt = 0; mt < 4; mt++)
                #pragma unroll
                for (int nt = 0; nt < 2; nt++)
                    mma8(acc[mt][nt], a[mt], b[nt]);
        }
    }
    #pragma unroll
    for (int mt = 0; mt < 4; mt++)
        #pragma unroll
        for (int nt = 0; nt < 2; nt++) {
            int n = n0 + nwarp * 16 + nt * 8 + (lane & 3) * 2;
            float bv0 = bias[n], bv1 = bias[n + 1];
            #pragma unroll
            for (int h = 0; h < 2; h++) {
                int m = m0 + mwarp * 64 + mt * 16 + (lane >> 2) + h * 8;
                float2 o;
                o.x = acc[mt][nt][h * 2 + 0] + bv0;
                o.y = acc[mt][nt][h * 2 + 1] + bv1;
                *(float2*)(C + (size_t)m * 256 + n) = o;
            }
        }
}

// ================= fp32 GEMM (node_fc only) =================
__global__ void gemm_kernel(const float* __restrict__ A, const float* __restrict__ Bm,
                            const float* __restrict__ bias, float* __restrict__ C,
                            int K, int N) {
    __shared__ float As[8][68];
    __shared__ float Bs[8][68];
    int tid = threadIdx.x;
    int row0 = blockIdx.x * 64;
    int col0 = blockIdx.y * 64;
    int tr = tid / 16, tc = tid % 16;
    int ar = tid / 8, ac = tid % 8;
    int br = tid / 64, bc = tid % 64;
    float acc[4][4];
    #pragma unroll
    for (int i = 0; i < 4; i++)
        #pragma unroll
        for (int j = 0; j < 4; j++) acc[i][j] = 0.f;
    for (int k0 = 0; k0 < K; k0 += 8) {
        #pragma unroll
        for (int i = 0; i < 2; i++)
            As[ac][ar + i * 32] = A[(size_t)(row0 + ar + i * 32) * K + k0 + ac];
        #pragma unroll
        for (int i = 0; i < 2; i++)
            Bs[br + i * 4][bc] = Bm[(size_t)(k0 + br + i * 4) * N + col0 + bc];
        __syncthreads();
        #pragma unroll
        for (int kk = 0; kk < 8; kk++) {
            float4 a = *(const float4*)&As[kk][tr * 4];
            float4 b = *(const float4*)&Bs[kk][tc * 4];
            acc[0][0] += a.x * b.x; acc[0][1] += a.x * b.y; acc[0][2] += a.x * b.z; acc[0][3] += a.x * b.w;
            acc[1][0] += a.y * b.x; acc[1][1] += a.y * b.y; acc[1][2] += a.y * b.z; acc[1][3] += a.y * b.w;
            acc[2][0] += a.z * b.x; acc[2][1] += a.z * b.y; acc[2][2] += a.z * b.z; acc[2][3] += a.z * b.w;
            acc[3][0] += a.w * b.x; acc[3][1] += a.w * b.y; acc[3][2] += a.w * b.z; acc[3][3] += a.w * b.w;
        }
        __syncthreads();
    }
    #pragma unroll
    for (int i = 0; i < 4; i++) {
        int r = row0 + tr * 4 + i;
        #pragma unroll
        for (int j = 0; j < 4; j++) {
            int cidx = col0 + tc * 4 + j;
            C[(size_t)r * N + cidx] = acc[i][j] + bias[cidx];
        }
    }
}

// ================= proto distances + softmax/gate + blend =================
__global__ void proto_kernel(const float* __restrict__ protos,
                             const float* __restrict__ temp_raw,
                             const float* __restrict__ gate) {
    __shared__ float zs[8 * 256];
    __shared__ float dsm[8 * 256];
    __shared__ float wsm[8 * 256];
    __shared__ float zn2[8];
    int b0 = blockIdx.x * 8;
    int tid = threadIdx.x;
    for (int i = tid; i < 2048; i += 256) zs[i] = g_z[(size_t)b0 * 256 + i];
    __syncthreads();
    if (tid < 8) {
        float s = 0.f;
        for (int k = 0; k < 256; k++) { float v = zs[tid * 256 + k]; s += v * v; }
        zn2[tid] = s;
    }
    __syncthreads();
    int j = tid;
    float ap[8], ag[8];
    #pragma unroll
    for (int r = 0; r < 8; r++) { ap[r] = 0.f; ag[r] = 0.f; }
    for (int k = 0; k < 256; k++) {
        float pv = g_protosT[k * 256 + j];
        float gv = g_gridT[k * 256 + j];
        #pragma unroll
        for (int r = 0; r < 8; r++) {
            float zv = zs[r * 256 + k];
            ap[r] += zv * pv;
            ag[r] += zv * gv;
        }
    }
    float pj = g_pn2[j], gj = g_gn2[j];
    #pragma unroll
    for (int r = 0; r < 8; r++) {
        float d1 = sqrtf(fmaxf(zn2[r] + pj - 2.f * ap[r], 0.f));
        float d2 = sqrtf(fmaxf(zn2[r] + gj - 2.f * ag[r], 0.f));
        dsm[r * 256 + j] = d1 + d2;
    }
    __syncthreads();
    float temp = 1.f / (1.f + expf(-temp_raw[0])) * 0.999f + 0.001f;
    float invt = 1.f / temp;
    int wr = tid >> 5;
    int lane = tid & 31;
    float mn = dsm[wr * 256 + lane];
    #pragma unroll
    for (int t = 1; t < 8; t++) mn = fminf(mn, dsm[wr * 256 + lane + t * 32]);
    #pragma unroll
    for (int o = 16; o; o >>= 1) mn = fminf(mn, __shfl_xor_sync(0xffffffffu, mn, o));
    float pvals[8];
    float S = 0.f;
    #pragma unroll
    for (int t = 0; t < 8; t++) {
        float e = expf((mn - dsm[wr * 256 + lane + t * 32]) * invt);
        pvals[t] = e; S += e;
    }
    #pragma unroll
    for (int o = 16; o; o >>= 1) S += __shfl_xor_sync(0xffffffffu, S, o);
    float invS = 1.f / S;
    float T = 0.f;
    #pragma unroll
    for (int t = 0; t < 8; t++) {
        int jj = lane + t * 32;
        float sg = 1.f / (1.f + expf(-gate[jj]));
        float bb = pvals[t] * invS * sg;
        pvals[t] = bb; T += bb;
    }
    #pragma unroll
    for (int o = 16; o; o >>= 1) T += __shfl_xor_sync(0xffffffffu, T, o);
    float inv = 1.f / (T + 1e-8f);
    #pragma unroll
    for (int t = 0; t < 8; t++) wsm[wr * 256 + lane + t * 32] = pvals[t] * inv;
    __syncthreads();
    int d = tid;
    float accb[8];
    #pragma unroll
    for (int r = 0; r < 8; r++) accb[r] = 0.f;
    for (int jj = 0; jj < 256; jj++) {
        float pv = protos[(size_t)jj * 256 + d];
        #pragma unroll
        for (int r = 0; r < 8; r++) accb[r] += wsm[r * 256 + jj] * pv;
    }
    #pragma unroll
    for (int r = 0; r < 8; r++) g_blend[(size_t)(b0 + r) * 256 + d] = accb[r];
}

__global__ void logits_kernel(const float* __restrict__ clf_b, float* __restrict__ out) {
    __shared__ float bs[32 * 256];
    __shared__ float ws[2560];
    int b0 = blockIdx.x * 32;
    int tid = threadIdx.x;  // 320
    for (int i = tid; i < 8192; i += 320) bs[i] = g_blend[(size_t)b0 * 256 + i];
    for (int i = tid; i < 2560; i += 320) ws[i] = g_wsum[i];
    __syncthreads();
    int r = tid / 10, c = tid % 10;
    float acc = clf_b[c];
    for (int d = 0; d < 256; d++) acc += bs[r * 256 + d] * ws[d * 10 + c];
    out[(size_t)(b0 + r) * 10 + c] = acc;
}

// ================= launch =================
extern "C" void kernel_launch(void* const* d_in, const int* in_sizes, int n_in,
                              void* d_out, int out_size) {
    const float* x        = (const float*)d_in[0];
    const float* conv1_w  = (const float*)d_in[2];
    const float* conv1_b  = (const float*)d_in[3];
    const float* conv2_w  = (const float*)d_in[4];
    const float* conv2_b  = (const float*)d_in[5];
    const float* conv3_w  = (const float*)d_in[6];
    const float* conv3_b  = (const float*)d_in[7];
    const float* conv4_w  = (const float*)d_in[8];
    const float* conv4_b  = (const float*)d_in[9];
    const float* enc_w    = (const float*)d_in[10];
    const float* enc_b    = (const float*)d_in[11];
    const float* clf_w    = (const float*)d_in[18];
    const float* clf_b    = (const float*)d_in[19];
    const float* node_fc_w = (const float*)d_in[20];
    const float* node_fc_b = (const float*)d_in[21];
    const float* protos   = (const float*)d_in[22];
    const float* grid_pos = (const float*)d_in[23];
    const float* temp_raw = (const float*)d_in[24];
    const float* gate     = (const float*)d_in[25];
    float* out = (float*)d_out;

    float *p_h2, *p_h3, *p_h4, *p_z0, *p_z, *p_encwT, *p_w3t, *p_w4t;
    cudaGetSymbolAddress((void**)&p_h2, g_h2);
    cudaGetSymbolAddress((void**)&p_h3, g_h3);
    cudaGetSymbolAddress((void**)&p_h4, g_h4);
    cudaGetSymbolAddress((void**)&p_z0, g_z0);
    cudaGetSymbolAddress((void**)&p_z, g_z);
    cudaGetSymbolAddress((void**)&p_encwT, g_encwT);
    cudaGetSymbolAddress((void**)&p_w3t, g_w3t);
    cudaGetSymbolAddress((void**)&p_w4t, g_w4t);

    // smem: conv3 = (128*68 + 3*128*36)*4 = 90112 ; conv4 = (128*132 + 3*256*36)*4 = 178176
    // enc = 3*(128+64)*36*4 = 82944
    static const int SM3 = 90112, SM4 = 178176, SME = 82944;
    cudaFuncSetAttribute(conv_mma<64, 128>, cudaFuncAttributeMaxDynamicSharedMemorySize, SM3);
    cudaFuncSetAttribute(conv_mma<128, 256>, cudaFuncAttributeMaxDynamicSharedMemorySize, SM4);
    cudaFuncSetAttribute(enc_mma, cudaFuncAttributeMaxDynamicSharedMemorySize, SME);

    prep_kernel<<<257, 256>>>(protos, grid_pos, clf_w);
    prep_encw<<<512, 256>>>(enc_w);
    prep_wc<<<(9 * 128 * 64 + 255) / 256, 256>>>(conv3_w, p_w3t, 128, 64);
    prep_wc<<<(9 * 256 * 128 + 255) / 256, 256>>>(conv4_w, p_w4t, 256, 128);

    conv1_kernel<<<B_, 256>>>(x, conv1_w, conv1_b);
    conv2_kernel<<<B_, 128>>>(conv2_w, conv2_b);
    conv_mma<64, 128><<<B_ / 2, 256, SM3>>>(p_h2, p_w3t, conv3_b, p_h3);
    conv_mma<128, 256><<<B_ / 2, 256, SM4>>>(p_h3, p_w4t, conv4_b, p_h4);

    enc_mma<<<dim3(32, 4), 256, SME>>>(p_h4, p_encwT, enc_b, p_z0);
    gemm_kernel<<<dim3(64, 4), 256>>>(p_z0, node_fc_w, node_fc_b, p_z, D_, D_);

    proto_kernel<<<B_ / 8, 256>>>(protos, temp_raw, gate);
    logits_kernel<<<B_ / 32, 320>>>(clf_b, out);
}

// round 7
// speedup vs baseline: 6.5628x; 1.8701x over previous
#include <cuda_runtime.h>
#include <cuda_bf16.h>
#include <math.h>
#include <cstdint>

#define B_ 4096
#define D_ 256
#define NPROTO 256

// ---------------- scratch (device globals; no allocations allowed) ----------------
__device__ __nv_bfloat16 g_h1bf[(size_t)B_ * 225 * 32];   // NHWC bf16
__device__ __nv_bfloat16 g_h2bf[(size_t)B_ * 64 * 64];    // NHWC bf16
__device__ __nv_bfloat16 g_h3bf[(size_t)B_ * 64 * 128];   // NHWC bf16
__device__ __nv_bfloat16 g_h4bf[(size_t)B_ * 64 * 256];   // NHWC bf16
__device__ float g_z0[B_ * D_];
__device__ float g_z[B_ * D_];
__device__ float g_blend[B_ * D_];
__device__ float g_protosT[NPROTO * D_];
__device__ float g_gridT[NPROTO * D_];
__device__ float g_pn2[NPROTO];
__device__ float g_gn2[NPROTO];
__device__ float g_wsum[D_ * 10];
__device__ __nv_bfloat16 g_encwT[(size_t)D_ * 16384];   // [d][k], k = p*256+c
__device__ __nv_bfloat16 g_w2t[9 * 64 * 32];            // [tap][oc][c]
__device__ __nv_bfloat16 g_w3t[9 * 128 * 64];
__device__ __nv_bfloat16 g_w4t[9 * 256 * 128];

// ================= helpers =================
__device__ __forceinline__ uint32_t smem_u32(const void* p) {
    uint32_t a;
    asm("{ .reg .u64 t; cvta.to.shared.u64 t, %1; cvt.u32.u64 %0, t; }" : "=r"(a) : "l"(p));
    return a;
}
__device__ __forceinline__ void cp16(uint32_t s, const void* g) {
    asm volatile("cp.async.cg.shared.global [%0], [%1], 16;" :: "r"(s), "l"(g));
}
#define CP_COMMIT() asm volatile("cp.async.commit_group;" ::: "memory")
#define CP_WAIT1()  asm volatile("cp.async.wait_group 1;" ::: "memory")

__device__ __forceinline__ uint32_t packbf(float lo, float hi) {
    uint32_t r; asm("cvt.rn.bf16x2.f32 %0, %1, %2;" : "=r"(r) : "f"(hi), "f"(lo)); return r;
}
// m16n8k16 bf16 mma, fp32 accum
__device__ __forceinline__ void mma16(float c[4], const uint32_t a[4], const uint32_t b[2]) {
    asm volatile(
        "mma.sync.aligned.m16n8k16.row.col.f32.bf16.bf16.f32 "
        "{%0,%1,%2,%3}, {%4,%5,%6,%7}, {%8,%9}, {%0,%1,%2,%3};"
        : "+f"(c[0]), "+f"(c[1]), "+f"(c[2]), "+f"(c[3])
        : "r"(a[0]), "r"(a[1]), "r"(a[2]), "r"(a[3]), "r"(b[0]), "r"(b[1]));
}
__device__ __forceinline__ uint32_t lds_u32(const __nv_bfloat16* p) {
    return *(const uint32_t*)p;
}

// ================= prep kernels =================
__global__ void prep_kernel(const float* __restrict__ protos,
                            const float* __restrict__ grid_pos,
                            const float* __restrict__ clf_w) {
    int bid = blockIdx.x;
    int tid = threadIdx.x;
    if (bid < NPROTO) {
        float pv = protos[bid * D_ + tid];
        float gv = grid_pos[bid * D_ + tid];
        g_protosT[tid * NPROTO + bid] = pv;
        g_gridT[tid * NPROTO + bid] = gv;
        __shared__ float red[256];
        red[tid] = pv * pv;
        __syncthreads();
        for (int s = 128; s > 0; s >>= 1) { if (tid < s) red[tid] += red[tid + s]; __syncthreads(); }
        if (tid == 0) g_pn2[bid] = red[0];
        __syncthreads();
        red[tid] = gv * gv;
        __syncthreads();
        for (int s = 128; s > 0; s >>= 1) { if (tid < s) red[tid] += red[tid + s]; __syncthreads(); }
        if (tid == 0) g_gn2[bid] = red[0];
    } else {
        for (int i = tid; i < D_ * 10; i += 256) {
            int dd = i / 10, c = i % 10;
            float s = 0.f;
            #pragma unroll
            for (int h = 0; h < 4; h++) s += clf_w[(h * 256 + dd) * 10 + c];
            g_wsum[i] = s;
        }
    }
}

// encwT[d][k] = bf16(enc_w[(c*64+p)*256 + d]), k = p*256+c
__global__ void prep_encw(const float* __restrict__ enc_w) {
    __shared__ float s[32][257];
    int k0 = blockIdx.x * 32;
    int tid = threadIdx.x;
    for (int r = 0; r < 32; r++) {
        int k = k0 + r;
        int c = k & 255, p = k >> 8;
        s[r][tid] = enc_w[(size_t)(c * 64 + p) * 256 + tid];
    }
    __syncthreads();
    int lane = tid & 31, w = tid >> 5;
    for (int d = w; d < 256; d += 8)
        g_encwT[(size_t)d * 16384 + k0 + lane] = __float2bfloat16(s[lane][d]);
}

// wt[((t*COUT+oc)*CIN)+c] = bf16(w[(oc*CIN+c)*9 + t])
__global__ void prep_wc(const float* __restrict__ w, __nv_bfloat16* __restrict__ wt, int COUT, int CIN) {
    int i = blockIdx.x * 256 + threadIdx.x;
    if (i >= 9 * COUT * CIN) return;
    int c = i % CIN;
    int oc = (i / CIN) % COUT;
    int t = i / (CIN * COUT);
    wt[i] = __float2bfloat16(w[((size_t)(oc * CIN + c)) * 9 + t]);
}

// ================= conv1: 3->32, 5x5, s2, p1 (fp32 compute, bf16 NHWC out) =================
__global__ void conv1_kernel(const float* __restrict__ x,
                             const float* __restrict__ w,
                             const float* __restrict__ bias) {
    __shared__ float xs[3 * 32 * 32];
    __shared__ float ws[32 * 3 * 25];
    int b = blockIdx.x, tid = threadIdx.x;
    const float* xb = x + (size_t)b * 3072;
    for (int i = tid; i < 3072; i += 256) xs[i] = xb[i];
    for (int i = tid; i < 2400; i += 256) ws[i] = w[i];
    __syncthreads();
    for (int o = tid; o < 32 * 225; o += 256) {
        int pos = o >> 5, oc = o & 31;           // NHWC-ordered for coalesced stores
        int oh = pos / 15, ow = pos % 15;
        float acc = bias[oc];
        #pragma unroll
        for (int c = 0; c < 3; c++)
            #pragma unroll
            for (int kh = 0; kh < 5; kh++) {
                int ih = 2 * oh - 1 + kh;
                if ((unsigned)ih < 32u) {
                    #pragma unroll
                    for (int kw = 0; kw < 5; kw++) {
                        int iw = 2 * ow - 1 + kw;
                        if ((unsigned)iw < 32u)
                            acc += xs[(c * 32 + ih) * 32 + iw] * ws[(oc * 3 + c) * 25 + kh * 5 + kw];
                    }
                }
            }
        g_h1bf[((size_t)b * 225 + pos) * 32 + oc] = __float2bfloat16(fmaxf(acc, 0.f));
    }
}

// ================= conv2 mma: 32->64, 3x3, s2, p1, 15x15 -> 8x8 NHWC bf16 =================
// M=128 (2 imgs x 64 px), N=64, 9 K-chunks of 32.
__global__ __launch_bounds__(256, 1) void conv2_mma(const __nv_bfloat16* __restrict__ in,
                                                    const __nv_bfloat16* __restrict__ wt,
                                                    const float* __restrict__ bias,
                                                    __nv_bfloat16* __restrict__ out) {
    extern __shared__ char dynsm[];
    __nv_bfloat16* RAW = (__nv_bfloat16*)dynsm;            // 2*225*40
    __nv_bfloat16* BS = RAW + 2 * 225 * 40;                // 3*64*40
    uint32_t rawb = smem_u32(RAW), bsb = smem_u32(BS);
    int tid = threadIdx.x, lane = tid & 31, wid = tid >> 5;
    int mwarp = wid & 1, nwarp = wid >> 1;
    int b0 = blockIdx.x * 2;

    const __nv_bfloat16* inb = in + (size_t)b0 * 225 * 32;
    for (int i = tid; i < 1800; i += 256) {
        int img = i / 900, rem = i % 900, px = rem >> 2, seg = rem & 3;
        cp16(rawb + (uint32_t)((img * 225 + px) * 40 + seg * 8) * 2,
             inb + (size_t)(img * 225 + px) * 32 + seg * 8);
    }
    auto issueB = [&](int j) {
        int oc = tid >> 2, seg = tid & 3;
        cp16(bsb + (uint32_t)((j % 3) * 64 * 40 + oc * 40 + seg * 8) * 2,
             wt + ((size_t)j * 64 + oc) * 32 + seg * 8);
    };
    issueB(0); CP_COMMIT();
    issueB(1); CP_COMMIT();

    float acc[4][2][4];
    #pragma unroll
    for (int mt = 0; mt < 4; mt++)
        #pragma unroll
        for (int nt = 0; nt < 2; nt++)
            #pragma unroll
            for (int q = 0; q < 4; q++) acc[mt][nt][q] = 0.f;

    for (int i = 0; i < 9; i++) {
        CP_WAIT1();
        __syncthreads();
        if (i + 2 < 9) { issueB(i + 2); }
        CP_COMMIT();
        int kh = i / 3, kw = i % 3;
        int aoff[4][2]; bool am[4][2];
        #pragma unroll
        for (int mt = 0; mt < 4; mt++)
            #pragma unroll
            for (int h = 0; h < 2; h++) {
                int r = mwarp * 64 + mt * 16 + (lane >> 2) + h * 8;
                int img = r >> 6, px = r & 63;
                int ih = 2 * (px >> 3) - 1 + kh, iw = 2 * (px & 7) - 1 + kw;
                am[mt][h] = ((unsigned)ih < 15u) && ((unsigned)iw < 15u);
                aoff[mt][h] = (img * 225 + ih * 15 + iw) * 40;
            }
        const __nv_bfloat16* bsc = BS + (i % 3) * (64 * 40);
        #pragma unroll
        for (int kk = 0; kk < 2; kk++) {
            int c0 = kk * 16 + (lane & 3) * 2;
            uint32_t a[4][4];
            #pragma unroll
            for (int mt = 0; mt < 4; mt++) {
                a[mt][0] = am[mt][0] ? lds_u32(RAW + aoff[mt][0] + c0) : 0u;
                a[mt][1] = am[mt][1] ? lds_u32(RAW + aoff[mt][1] + c0) : 0u;
                a[mt][2] = am[mt][0] ? lds_u32(RAW + aoff[mt][0] + c0 + 8) : 0u;
                a[mt][3] = am[mt][1] ? lds_u32(RAW + aoff[mt][1] + c0 + 8) : 0u;
            }
            uint32_t b[2][2];
            #pragma unroll
            for (int nt = 0; nt < 2; nt++) {
                int n = nwarp * 16 + nt * 8 + (lane >> 2);
                b[nt][0] = lds_u32(bsc + n * 40 + c0);
                b[nt][1] = lds_u32(bsc + n * 40 + c0 + 8);
            }
            #pragma unroll
            for (int mt = 0; mt < 4; mt++)
                #pragma unroll
                for (int nt = 0; nt < 2; nt++)
                    mma16(acc[mt][nt], a[mt], b[nt]);
        }
    }
    #pragma unroll
    for (int mt = 0; mt < 4; mt++)
        #pragma unroll
        for (int nt = 0; nt < 2; nt++) {
            int n = nwarp * 16 + nt * 8 + (lane & 3) * 2;
            float bv0 = bias[n], bv1 = bias[n + 1];
            #pragma unroll
            for (int h = 0; h < 2; h++) {
                int r = mwarp * 64 + mt * 16 + (lane >> 2) + h * 8;
                int img = r >> 6, px = r & 63;
                uint32_t pk = packbf(fmaxf(acc[mt][nt][h * 2 + 0] + bv0, 0.f),
                                     fmaxf(acc[mt][nt][h * 2 + 1] + bv1, 0.f));
                *(uint32_t*)(out + ((size_t)(b0 + img) * 64 + px) * 64 + n) = pk;
            }
        }
}

// ================= bf16 mma implicit-GEMM conv 3x3 s1 p1 (NHWC) =================
template <int CIN, int COUT>
__global__ __launch_bounds__(256, 1) void conv_mma(const __nv_bfloat16* __restrict__ in,
                                                   const __nv_bfloat16* __restrict__ wt,
                                                   const float* __restrict__ bias,
                                                   __nv_bfloat16* __restrict__ out) {
    constexpr int CINP = CIN + 8;
    constexpr int CB = CIN / 32, NCH = 9 * CB;
    constexpr int NW = COUT / 4, NT = NW / 8;
    extern __shared__ char dynsm[];
    __nv_bfloat16* RAW = (__nv_bfloat16*)dynsm;       // 128 * CINP
    __nv_bfloat16* BS = RAW + 128 * CINP;             // 3 * COUT * 40
    uint32_t rawb = smem_u32(RAW), bsb = smem_u32(BS);
    int tid = threadIdx.x, lane = tid & 31, wid = tid >> 5;
    int mwarp = wid & 1, nwarp = wid >> 1;
    int b0 = blockIdx.x * 2;

    const __nv_bfloat16* inb = in + (size_t)b0 * 64 * CIN;
    constexpr int SEGS = CIN / 8;
    #pragma unroll
    for (int u = 0; u < 128 * SEGS / 256; u++) {
        int i = u * 256 + tid;
        int px = i / SEGS, seg = i % SEGS;
        cp16(rawb + (uint32_t)(px * CINP + seg * 8) * 2, inb + (size_t)px * CIN + seg * 8);
    }
    auto issueB = [&](int j) {
        int cb = j % CB, t = j / CB;
        const __nv_bfloat16* wb = wt + ((size_t)t * COUT) * CIN + cb * 32;
        uint32_t dst = bsb + (uint32_t)((j % 3) * COUT * 40) * 2;
        #pragma unroll
        for (int u = 0; u < COUT * 4 / 256; u++) {
            int i = u * 256 + tid;
            int oc = i >> 2, seg = i & 3;
            cp16(dst + (uint32_t)(oc * 40 + seg * 8) * 2, wb + (size_t)oc * CIN + seg * 8);
        }
    };
    issueB(0); CP_COMMIT();
    issueB(1); CP_COMMIT();

    float acc[4][NT][4];
    #pragma unroll
    for (int mt = 0; mt < 4; mt++)
        #pragma unroll
        for (int nt = 0; nt < NT; nt++)
            #pragma unroll
            for (int q = 0; q < 4; q++) acc[mt][nt][q] = 0.f;

    for (int i = 0; i < NCH; i++) {
        CP_WAIT1();
        __syncthreads();
        if (i + 2 < NCH) { issueB(i + 2); }
        CP_COMMIT();
        int cb = i % CB, t = i / CB, kh = t / 3, kw = t % 3;
        int aoff[4][2]; bool am[4][2];
        #pragma unroll
        for (int mt = 0; mt < 4; mt++)
            #pragma unroll
            for (int h = 0; h < 2; h++) {
                int r = mwarp * 64 + mt * 16 + (lane >> 2) + h * 8;
                int img = r >> 6, px = r & 63;
                int ih = (px >> 3) + kh - 1, iw = (px & 7) + kw - 1;
                am[mt][h] = ((unsigned)ih < 8u) && ((unsigned)iw < 8u);
                aoff[mt][h] = ((img << 6) + (ih << 3) + iw) * CINP + cb * 32;
            }
        const __nv_bfloat16* bsc = BS + (i % 3) * (COUT * 40);
        #pragma unroll
        for (int kk = 0; kk < 2; kk++) {
            int c0 = kk * 16 + (lane & 3) * 2;
            uint32_t a[4][4];
            #pragma unroll
            for (int mt = 0; mt < 4; mt++) {
                a[mt][0] = am[mt][0] ? lds_u32(RAW + aoff[mt][0] + c0) : 0u;
                a[mt][1] = am[mt][1] ? lds_u32(RAW + aoff[mt][1] + c0) : 0u;
                a[mt][2] = am[mt][0] ? lds_u32(RAW + aoff[mt][0] + c0 + 8) : 0u;
                a[mt][3] = am[mt][1] ? lds_u32(RAW + aoff[mt][1] + c0 + 8) : 0u;
            }
            uint32_t b[NT][2];
            #pragma unroll
            for (int nt = 0; nt < NT; nt++) {
                int n = nwarp * NW + nt * 8 + (lane >> 2);
                b[nt][0] = lds_u32(bsc + n * 40 + c0);
                b[nt][1] = lds_u32(bsc + n * 40 + c0 + 8);
            }
            #pragma unroll
            for (int mt = 0; mt < 4; mt++)
                #pragma unroll
                for (int nt = 0; nt < NT; nt++)
                    mma16(acc[mt][nt], a[mt], b[nt]);
        }
    }
    #pragma unroll
    for (int mt = 0; mt < 4; mt++)
        #pragma unroll
        for (int nt = 0; nt < NT; nt++) {
            int n = nwarp * NW + nt * 8 + (lane & 3) * 2;
            float bv0 = bias[n], bv1 = bias[n + 1];
            #pragma unroll
            for (int h = 0; h < 2; h++) {
                int r = mwarp * 64 + mt * 16 + (lane >> 2) + h * 8;
                int img = r >> 6, px = r & 63;
                uint32_t pk = packbf(fmaxf(acc[mt][nt][h * 2 + 0] + bv0, 0.f),
                                     fmaxf(acc[mt][nt][h * 2 + 1] + bv1, 0.f));
                *(uint32_t*)(out + ((size_t)(b0 + img) * 64 + px) * COUT + n) = pk;
            }
        }
}

// ================= bf16 mma GEMM: z0[4096,256] = h4 @ encwT^T, M-tile 64, N-tile 64, K-chunk 64 ====
__global__ __launch_bounds__(256, 1) void enc_mma(const __nv_bfloat16* __restrict__ A,
                                                  const __nv_bfloat16* __restrict__ Bw,
                                                  const float* __restrict__ bias,
                                                  float* __restrict__ C) {
    constexpr int K = 16384, NCH = K / 64;
    extern __shared__ char dynsm[];
    __nv_bfloat16* AS = (__nv_bfloat16*)dynsm;        // 3 * 64*72
    __nv_bfloat16* BSm = AS + 3 * 64 * 72;            // 3 * 64*72
    uint32_t asb = smem_u32(AS), bsb = smem_u32(BSm);
    int tid = threadIdx.x, lane = tid & 31, wid = tid >> 5;
    int mwarp = wid & 1, nwarp = wid >> 1;
    int m0 = blockIdx.x * 64, n0 = blockIdx.y * 64;

    auto issue = [&](int j) {
        int buf = j % 3;
        const __nv_bfloat16* Ab = A + (size_t)m0 * K + j * 64;
        const __nv_bfloat16* Bb = Bw + (size_t)n0 * K + j * 64;
        #pragma unroll
        for (int u = 0; u < 2; u++) {
            int i = u * 256 + tid;
            int r = i >> 3, seg = i & 7;
            cp16(asb + (uint32_t)(buf * 64 * 72 + r * 72 + seg * 8) * 2, Ab + (size_t)r * K + seg * 8);
        }
        #pragma unroll
        for (int u = 0; u < 2; u++) {
            int i = u * 256 + tid;
            int r = i >> 3, seg = i & 7;
            cp16(bsb + (uint32_t)(buf * 64 * 72 + r * 72 + seg * 8) * 2, Bb + (size_t)r * K + seg * 8);
        }
    };
    issue(0); CP_COMMIT();
    issue(1); CP_COMMIT();

    float acc[2][2][4];
    #pragma unroll
    for (int mt = 0; mt < 2; mt++)
        #pragma unroll
        for (int nt = 0; nt < 2; nt++)
            #pragma unroll
            for (int q = 0; q < 4; q++) acc[mt][nt][q] = 0.f;

    for (int i = 0; i < NCH; i++) {
        CP_WAIT1();
        __syncthreads();
        if (i + 2 < NCH) { issue(i + 2); }
        CP_COMMIT();
        const __nv_bfloat16* asc = AS + (i % 3) * (64 * 72);
        const __nv_bfloat16* bsc = BSm + (i % 3) * (64 * 72);
        #pragma unroll
        for (int kk = 0; kk < 4; kk++) {
            int c0 = kk * 16 + (lane & 3) * 2;
            uint32_t a[2][4];
            #pragma unroll
            for (int mt = 0; mt < 2; mt++) {
                int r = mwarp * 32 + mt * 16 + (lane >> 2);
                a[mt][0] = lds_u32(asc + r * 72 + c0);
                a[mt][1] = lds_u32(asc + (r + 8) * 72 + c0);
                a[mt][2] = lds_u32(asc + r * 72 + c0 + 8);
                a[mt][3] = lds_u32(asc + (r + 8) * 72 + c0 + 8);
            }
            uint32_t b[2][2];
            #pragma unroll
            for (int nt = 0; nt < 2; nt++) {
                int n = nwarp * 16 + nt * 8 + (lane >> 2);
                b[nt][0] = lds_u32(bsc + n * 72 + c0);
                b[nt][1] = lds_u32(bsc + n * 72 + c0 + 8);
            }
            #pragma unroll
            for (int mt = 0; mt < 2; mt++)
                #pragma unroll
                for (int nt = 0; nt < 2; nt++)
                    mma16(acc[mt][nt], a[mt], b[nt]);
        }
    }
    #pragma unroll
    for (int mt = 0; mt < 2; mt++)
        #pragma unroll
        for (int nt = 0; nt < 2; nt++) {
            int n = n0 + nwarp * 16 + nt * 8 + (lane & 3) * 2;
            float bv0 = bias[n], bv1 = bias[n + 1];
            #pragma unroll
            for (int h = 0; h < 2; h++) {
                int m = m0 + mwarp * 32 + mt * 16 + (lane >> 2) + h * 8;
                float2 o;
                o.x = acc[mt][nt][h * 2 + 0] + bv0;
                o.y = acc[mt][nt][h * 2 + 1] + bv1;
                *(float2*)(C + (size_t)m * 256 + n) = o;
            }
        }
}

// ================= fp32 GEMM (node_fc only) =================
__global__ void gemm_kernel(const float* __restrict__ A, const float* __restrict__ Bm,
                            const float* __restrict__ bias, float* __restrict__ C,
                            int K, int N) {
    __shared__ float As[8][68];
    __shared__ float Bs[8][68];
    int tid = threadIdx.x;
    int row0 = blockIdx.x * 64;
    int col0 = blockIdx.y * 64;
    int tr = tid / 16, tc = tid % 16;
    int ar = tid / 8, ac = tid % 8;
    int br = tid / 64, bc = tid % 64;
    float acc[4][4];
    #pragma unroll
    for (int i = 0; i < 4; i++)
        #pragma unroll
        for (int j = 0; j < 4; j++) acc[i][j] = 0.f;
    for (int k0 = 0; k0 < K; k0 += 8) {
        #pragma unroll
        for (int i = 0; i < 2; i++)
            As[ac][ar + i * 32] = A[(size_t)(row0 + ar + i * 32) * K + k0 + ac];
        #pragma unroll
        for (int i = 0; i < 2; i++)
            Bs[br + i * 4][bc] = Bm[(size_t)(k0 + br + i * 4) * N + col0 + bc];
        __syncthreads();
        #pragma unroll
        for (int kk = 0; kk < 8; kk++) {
            float4 a = *(const float4*)&As[kk][tr * 4];
            float4 b = *(const float4*)&Bs[kk][tc * 4];
            acc[0][0] += a.x * b.x; acc[0][1] += a.x * b.y; acc[0][2] += a.x * b.z; acc[0][3] += a.x * b.w;
            acc[1][0] += a.y * b.x; acc[1][1] += a.y * b.y; acc[1][2] += a.y * b.z; acc[1][3] += a.y * b.w;
            acc[2][0] += a.z * b.x; acc[2][1] += a.z * b.y; acc[2][2] += a.z * b.z; acc[2][3] += a.z * b.w;
            acc[3][0] += a.w * b.x; acc[3][1] += a.w * b.y; acc[3][2] += a.w * b.z; acc[3][3] += a.w * b.w;
        }
        __syncthreads();
    }
    #pragma unroll
    for (int i = 0; i < 4; i++) {
        int r = row0 + tr * 4 + i;
        #pragma unroll
        for (int j = 0; j < 4; j++) {
            int cidx = col0 + tc * 4 + j;
            C[(size_t)r * N + cidx] = acc[i][j] + bias[cidx];
        }
    }
}

// ================= proto distances + softmax/gate + blend =================
__global__ void proto_kernel(const float* __restrict__ protos,
                             const float* __restrict__ temp_raw,
                             const float* __restrict__ gate) {
    __shared__ float zs[8 * 256];
    __shared__ float dsm[8 * 256];
    __shared__ float wsm[8 * 256];
    __shared__ float zn2[8];
    int b0 = blockIdx.x * 8;
    int tid = threadIdx.x;
    for (int i = tid; i < 2048; i += 256) zs[i] = g_z[(size_t)b0 * 256 + i];
    __syncthreads();
    if (tid < 8) {
        float s = 0.f;
        for (int k = 0; k < 256; k++) { float v = zs[tid * 256 + k]; s += v * v; }
        zn2[tid] = s;
    }
    __syncthreads();
    int j = tid;
    float ap[8], ag[8];
    #pragma unroll
    for (int r = 0; r < 8; r++) { ap[r] = 0.f; ag[r] = 0.f; }
    for (int k = 0; k < 256; k++) {
        float pv = g_protosT[k * 256 + j];
        float gv = g_gridT[k * 256 + j];
        #pragma unroll
        for (int r = 0; r < 8; r++) {
            float zv = zs[r * 256 + k];
            ap[r] += zv * pv;
            ag[r] += zv * gv;
        }
    }
    float pj = g_pn2[j], gj = g_gn2[j];
    #pragma unroll
    for (int r = 0; r < 8; r++) {
        float d1 = sqrtf(fmaxf(zn2[r] + pj - 2.f * ap[r], 0.f));
        float d2 = sqrtf(fmaxf(zn2[r] + gj - 2.f * ag[r], 0.f));
        dsm[r * 256 + j] = d1 + d2;
    }
    __syncthreads();
    float temp = 1.f / (1.f + expf(-temp_raw[0])) * 0.999f + 0.001f;
    float invt = 1.f / temp;
    int wr = tid >> 5;
    int lane = tid & 31;
    float mn = dsm[wr * 256 + lane];
    #pragma unroll
    for (int t = 1; t < 8; t++) mn = fminf(mn, dsm[wr * 256 + lane + t * 32]);
    #pragma unroll
    for (int o = 16; o; o >>= 1) mn = fminf(mn, __shfl_xor_sync(0xffffffffu, mn, o));
    float pvals[8];
    float S = 0.f;
    #pragma unroll
    for (int t = 0; t < 8; t++) {
        float e = expf((mn - dsm[wr * 256 + lane + t * 32]) * invt);
        pvals[t] = e; S += e;
    }
    #pragma unroll
    for (int o = 16; o; o >>= 1) S += __shfl_xor_sync(0xffffffffu, S, o);
    float invS = 1.f / S;
    float T = 0.f;
    #pragma unroll
    for (int t = 0; t < 8; t++) {
        int jj = lane + t * 32;
        float sg = 1.f / (1.f + expf(-gate[jj]));
        float bb = pvals[t] * invS * sg;
        pvals[t] = bb; T += bb;
    }
    #pragma unroll
    for (int o = 16; o; o >>= 1) T += __shfl_xor_sync(0xffffffffu, T, o);
    float inv = 1.f / (T + 1e-8f);
    #pragma unroll
    for (int t = 0; t < 8; t++) wsm[wr * 256 + lane + t * 32] = pvals[t] * inv;
    __syncthreads();
    int d = tid;
    float accb[8];
    #pragma unroll
    for (int r = 0; r < 8; r++) accb[r] = 0.f;
    for (int jj = 0; jj < 256; jj++) {
        float pv = protos[(size_t)jj * 256 + d];
        #pragma unroll
        for (int r = 0; r < 8; r++) accb[r] += wsm[r * 256 + jj] * pv;
    }
    #pragma unroll
    for (int r = 0; r < 8; r++) g_blend[(size_t)(b0 + r) * 256 + d] = accb[r];
}

__global__ void logits_kernel(const float* __restrict__ clf_b, float* __restrict__ out) {
    __shared__ float bs[32 * 256];
    __shared__ float ws[2560];
    int b0 = blockIdx.x * 32;
    int tid = threadIdx.x;  // 320
    for (int i = tid; i < 8192; i += 320) bs[i] = g_blend[(size_t)b0 * 256 + i];
    for (int i = tid; i < 2560; i += 320) ws[i] = g_wsum[i];
    __syncthreads();
    int r = tid / 10, c = tid % 10;
    float acc = clf_b[c];
    for (int d = 0; d < 256; d++) acc += bs[r * 256 + d] * ws[d * 10 + c];
    out[(size_t)(b0 + r) * 10 + c] = acc;
}

// ================= launch =================
extern "C" void kernel_launch(void* const* d_in, const int* in_sizes, int n_in,
                              void* d_out, int out_size) {
    const float* x        = (const float*)d_in[0];
    const float* conv1_w  = (const float*)d_in[2];
    const float* conv1_b  = (const float*)d_in[3];
    const float* conv2_w  = (const float*)d_in[4];
    const float* conv2_b  = (const float*)d_in[5];
    const float* conv3_w  = (const float*)d_in[6];
    const float* conv3_b  = (const float*)d_in[7];
    const float* conv4_w  = (const float*)d_in[8];
    const float* conv4_b  = (const float*)d_in[9];
    const float* enc_w    = (const float*)d_in[10];
    const float* enc_b    = (const float*)d_in[11];
    const float* clf_w    = (const float*)d_in[18];
    const float* clf_b    = (const float*)d_in[19];
    const float* node_fc_w = (const float*)d_in[20];
    const float* node_fc_b = (const float*)d_in[21];
    const float* protos   = (const float*)d_in[22];
    const float* grid_pos = (const float*)d_in[23];
    const float* temp_raw = (const float*)d_in[24];
    const float* gate     = (const float*)d_in[25];
    float* out = (float*)d_out;

    __nv_bfloat16 *p_h1, *p_h2, *p_h3, *p_h4, *p_encwT, *p_w2t, *p_w3t, *p_w4t;
    float *p_z0, *p_z;
    cudaGetSymbolAddress((void**)&p_h1, g_h1bf);
    cudaGetSymbolAddress((void**)&p_h2, g_h2bf);
    cudaGetSymbolAddress((void**)&p_h3, g_h3bf);
    cudaGetSymbolAddress((void**)&p_h4, g_h4bf);
    cudaGetSymbolAddress((void**)&p_z0, g_z0);
    cudaGetSymbolAddress((void**)&p_z, g_z);
    cudaGetSymbolAddress((void**)&p_encwT, g_encwT);
    cudaGetSymbolAddress((void**)&p_w2t, g_w2t);
    cudaGetSymbolAddress((void**)&p_w3t, g_w3t);
    cudaGetSymbolAddress((void**)&p_w4t, g_w4t);

    // dynamic smem (bytes): conv2 = (2*225*40 + 3*64*40)*2 = 51360
    // conv3 = (128*72 + 3*128*40)*2 = 49152 ; conv4 = (128*136 + 3*256*40)*2 = 96256
    // enc  = 3*2*64*72*2 = 55296
    static const int SM2 = 51360, SM3 = 49152, SM4 = 96256, SME = 55296;
    cudaFuncSetAttribute(conv2_mma, cudaFuncAttributeMaxDynamicSharedMemorySize, SM2);
    cudaFuncSetAttribute(conv_mma<64, 128>, cudaFuncAttributeMaxDynamicSharedMemorySize, SM3);
    cudaFuncSetAttribute(conv_mma<128, 256>, cudaFuncAttributeMaxDynamicSharedMemorySize, SM4);
    cudaFuncSetAttribute(enc_mma, cudaFuncAttributeMaxDynamicSharedMemorySize, SME);

    prep_kernel<<<257, 256>>>(protos, grid_pos, clf_w);
    prep_encw<<<512, 256>>>(enc_w);
    prep_wc<<<(9 * 64 * 32 + 255) / 256, 256>>>(conv2_w, p_w2t, 64, 32);
    prep_wc<<<(9 * 128 * 64 + 255) / 256, 256>>>(conv3_w, p_w3t, 128, 64);
    prep_wc<<<(9 * 256 * 128 + 255) / 256, 256>>>(conv4_w, p_w4t, 256, 128);

    conv1_kernel<<<B_, 256>>>(x, conv1_w, conv1_b);
    conv2_mma<<<B_ / 2, 256, SM2>>>(p_h1, p_w2t, conv2_b, p_h2);
    conv_mma<64, 128><<<B_ / 2, 256, SM3>>>(p_h2, p_w3t, conv3_b, p_h3);
    conv_mma<128, 256><<<B_ / 2, 256, SM4>>>(p_h3, p_w4t, conv4_b, p_h4);

    enc_mma<<<dim3(64, 4), 256, SME>>>(p_h4, p_encwT, enc_b, p_z0);
    gemm_kernel<<<dim3(64, 4), 256>>>(p_z0, node_fc_w, node_fc_b, p_z, D_, D_);

    proto_kernel<<<B_ / 8, 256>>>(protos, temp_raw, gate);
    logits_kernel<<<B_ / 32, 320>>>(clf_b, out);
}

// round 10
// speedup vs baseline: 7.7922x; 1.1873x over previous
#include <cuda_runtime.h>
#include <cuda_bf16.h>
#include <math.h>
#include <cstdint>

#define B_ 4096
#define D_ 256
#define NPROTO 256

// ---------------- scratch (device globals; no allocations allowed) ----------------
__device__ __nv_bfloat16 g_h1bf[(size_t)B_ * 225 * 32];   // NHWC bf16
__device__ __nv_bfloat16 g_h2bf[(size_t)B_ * 64 * 64];    // NHWC bf16
__device__ __nv_bfloat16 g_h3bf[(size_t)B_ * 64 * 128];   // NHWC bf16
__device__ __nv_bfloat16 g_h4bf[(size_t)B_ * 64 * 256];   // NHWC bf16
__device__ float g_z0[B_ * D_];
__device__ float g_z[B_ * D_];
__device__ float g_blend[B_ * D_];
__device__ float g_protosT[NPROTO * D_];
__device__ float g_gridT[NPROTO * D_];
__device__ float g_pn2[NPROTO];
__device__ float g_gn2[NPROTO];
__device__ float g_wsum[D_ * 10];
__device__ __nv_bfloat16 g_encwT[(size_t)D_ * 16384];   // [d][k], k = p*256+c
__device__ __nv_bfloat16 g_w2t[9 * 64 * 32];            // [tap][oc][c]
__device__ __nv_bfloat16 g_w3t[9 * 128 * 64];
__device__ __nv_bfloat16 g_w4t[9 * 256 * 128];

// ================= helpers =================
__device__ __forceinline__ uint32_t smem_u32(const void* p) {
    uint32_t a;
    asm("{ .reg .u64 t; cvta.to.shared.u64 t, %1; cvt.u32.u64 %0, t; }" : "=r"(a) : "l"(p));
    return a;
}
__device__ __forceinline__ void cp16(uint32_t s, const void* g) {
    asm volatile("cp.async.cg.shared.global [%0], [%1], 16;" :: "r"(s), "l"(g));
}
#define CP_COMMIT() asm volatile("cp.async.commit_group;" ::: "memory")
#define CP_WAIT1()  asm volatile("cp.async.wait_group 1;" ::: "memory")

__device__ __forceinline__ uint32_t packbf(float lo, float hi) {
    uint32_t r; asm("cvt.rn.bf16x2.f32 %0, %1, %2;" : "=r"(r) : "f"(hi), "f"(lo)); return r;
}
__device__ __forceinline__ void mma16(float c[4], const uint32_t a[4], const uint32_t b[2]) {
    asm volatile(
        "mma.sync.aligned.m16n8k16.row.col.f32.bf16.bf16.f32 "
        "{%0,%1,%2,%3}, {%4,%5,%6,%7}, {%8,%9}, {%0,%1,%2,%3};"
        : "+f"(c[0]), "+f"(c[1]), "+f"(c[2]), "+f"(c[3])
        : "r"(a[0]), "r"(a[1]), "r"(a[2]), "r"(a[3]), "r"(b[0]), "r"(b[1]));
}
__device__ __forceinline__ void ldsm_x4(uint32_t r[4], uint32_t addr) {
    asm volatile("ldmatrix.sync.aligned.m8n8.x4.shared.b16 {%0,%1,%2,%3}, [%4];"
        : "=r"(r[0]), "=r"(r[1]), "=r"(r[2]), "=r"(r[3]) : "r"(addr));
}
__device__ __forceinline__ void ldsm_x2(uint32_t r[2], uint32_t addr) {
    asm volatile("ldmatrix.sync.aligned.m8n8.x2.shared.b16 {%0,%1}, [%2];"
        : "=r"(r[0]), "=r"(r[1]) : "r"(addr));
}

// zero pad: must cover zaddr + kk*32 + 16 bytes for kk in {0,1}  => 64 bytes, 16 u32
#define ZP_WORDS 16

// ================= merged prep kernel =================
// bid ranges: [0,256) transpose+norms | 256 wsum | [257,769) encw | then wc: conv2 72, conv3 288, conv4 1152
__global__ void prep_all(const float* __restrict__ protos,
                         const float* __restrict__ grid_pos,
                         const float* __restrict__ clf_w,
                         const float* __restrict__ enc_w,
                         const float* __restrict__ w2,
                         const float* __restrict__ w3,
                         const float* __restrict__ w4) {
    __shared__ float sbuf[32 * 257];
    int bid = blockIdx.x;
    int tid = threadIdx.x;
    if (bid < 256) {
        float pv = protos[bid * D_ + tid];
        float gv = grid_pos[bid * D_ + tid];
        g_protosT[tid * NPROTO + bid] = pv;
        g_gridT[tid * NPROTO + bid] = gv;
        float* red = sbuf;
        red[tid] = pv * pv;
        __syncthreads();
        for (int s = 128; s > 0; s >>= 1) { if (tid < s) red[tid] += red[tid + s]; __syncthreads(); }
        if (tid == 0) g_pn2[bid] = red[0];
        __syncthreads();
        red[tid] = gv * gv;
        __syncthreads();
        for (int s = 128; s > 0; s >>= 1) { if (tid < s) red[tid] += red[tid + s]; __syncthreads(); }
        if (tid == 0) g_gn2[bid] = red[0];
    } else if (bid == 256) {
        for (int i = tid; i < D_ * 10; i += 256) {
            int dd = i / 10, c = i % 10;
            float s = 0.f;
            #pragma unroll
            for (int h = 0; h < 4; h++) s += clf_w[(h * 256 + dd) * 10 + c];
            g_wsum[i] = s;
        }
    } else if (bid < 769) {
        float (*s)[257] = (float (*)[257])sbuf;
        int k0 = (bid - 257) * 32;
        for (int r = 0; r < 32; r++) {
            int k = k0 + r;
            int c = k & 255, p = k >> 8;
            s[r][tid] = enc_w[(size_t)(c * 64 + p) * 256 + tid];
        }
        __syncthreads();
        int lane = tid & 31, w = tid >> 5;
        for (int d = w; d < 256; d += 8)
            g_encwT[(size_t)d * 16384 + k0 + lane] = __float2bfloat16(s[lane][d]);
    } else {
        const float* w; __nv_bfloat16* wt; int COUT, CIN, base;
        if (bid < 841)       { w = w2; wt = g_w2t; COUT = 64;  CIN = 32;  base = 769; }
        else if (bid < 1129) { w = w3; wt = g_w3t; COUT = 128; CIN = 64;  base = 841; }
        else                 { w = w4; wt = g_w4t; COUT = 256; CIN = 128; base = 1129; }
        int i = (bid - base) * 256 + tid;
        if (i < 9 * COUT * CIN) {
            int c = i % CIN;
            int oc = (i / CIN) % COUT;
            int t = i / (CIN * COUT);
            wt[i] = __float2bfloat16(w[((size_t)(oc * CIN + c)) * 9 + t]);
        }
    }
}

// ================= conv1: 3->32, 5x5, s2, p1 — branch-free padded, reg weights =================
__global__ __launch_bounds__(256) void conv1_kernel(const float* __restrict__ x,
                                                    const float* __restrict__ w,
                                                    const float* __restrict__ bias) {
    __shared__ __align__(16) float xs[3 * 34 * 36];   // [c][ih 0..33][iw 0..35], image at (+1,+1)
    __shared__ float ws[2400];
    int b = blockIdx.x, tid = threadIdx.x;
    for (int i = tid; i < 3 * 34 * 36; i += 256) xs[i] = 0.f;
    for (int i = tid; i < 2400; i += 256) ws[i] = w[i];
    __syncthreads();
    const float* xb = x + (size_t)b * 3072;
    for (int i = tid; i < 3072; i += 256) {
        int c = i >> 10, rem = i & 1023, ih = rem >> 5, iw = rem & 31;
        xs[c * 1224 + (ih + 1) * 36 + (iw + 1)] = xb[i];
    }
    __syncthreads();
    int oc = tid & 31, wg = tid >> 5;
    float wr[75];
    #pragma unroll
    for (int t = 0; t < 75; t++) wr[t] = ws[oc * 75 + t];
    float bv = bias[oc];
    __nv_bfloat16* ob = g_h1bf + (size_t)b * 225 * 32 + oc;
    for (int oh = wg; oh < 15; oh += 8) {
        float acc[8];
        #pragma unroll
        for (int j = 0; j < 8; j++) acc[j] = bv;
        #pragma unroll
        for (int c = 0; c < 3; c++)
            #pragma unroll
            for (int kh = 0; kh < 5; kh++) {
                const float* row = xs + c * 1224 + (2 * oh + kh) * 36;
                float xv[20];
                #pragma unroll
                for (int q = 0; q < 5; q++) *(float4*)(xv + q * 4) = *(const float4*)(row + q * 4);
                #pragma unroll
                for (int kw = 0; kw < 5; kw++) {
                    float wv = wr[c * 25 + kh * 5 + kw];
                    #pragma unroll
                    for (int ow = 0; ow < 8; ow++) acc[ow] += xv[2 * ow + kw] * wv;
                }
            }
        #pragma unroll
        for (int ow = 0; ow < 8; ow++)
            ob[(size_t)(oh * 15 + ow) * 32] = __float2bfloat16(fmaxf(acc[ow], 0.f));
        float acc2[7];
        #pragma unroll
        for (int j = 0; j < 7; j++) acc2[j] = bv;
        #pragma unroll
        for (int c = 0; c < 3; c++)
            #pragma unroll
            for (int kh = 0; kh < 5; kh++) {
                const float* row = xs + c * 1224 + (2 * oh + kh) * 36 + 16;
                float xv[20];
                #pragma unroll
                for (int q = 0; q < 5; q++) *(float4*)(xv + q * 4) = *(const float4*)(row + q * 4);
                #pragma unroll
                for (int kw = 0; kw < 5; kw++) {
                    float wv = wr[c * 25 + kh * 5 + kw];
                    #pragma unroll
                    for (int j = 0; j < 7; j++) acc2[j] += xv[2 * j + kw] * wv;
                }
            }
        #pragma unroll
        for (int j = 0; j < 7; j++)
            ob[(size_t)(oh * 15 + 8 + j) * 32] = __float2bfloat16(fmaxf(acc2[j], 0.f));
    }
}

// ================= conv2 mma: 32->64, 3x3, s2, p1, 15x15 -> 8x8 NHWC bf16 =================
__global__ __launch_bounds__(256, 2) void conv2_mma(const __nv_bfloat16* __restrict__ in,
                                                    const __nv_bfloat16* __restrict__ wt,
                                                    const float* __restrict__ bias,
                                                    __nv_bfloat16* __restrict__ out) {
    extern __shared__ char dynsm[];
    __nv_bfloat16* RAW = (__nv_bfloat16*)dynsm;            // 2*225*40
    __nv_bfloat16* BS = RAW + 2 * 225 * 40;                // 3*64*40
    uint32_t* ZP = (uint32_t*)(BS + 3 * 64 * 40);          // 64B zero pad
    uint32_t rawb = smem_u32(RAW), bsb = smem_u32(BS), zaddr = smem_u32(ZP);
    int tid = threadIdx.x, lane = tid & 31, wid = tid >> 5;
    int mwarp = wid & 1, nwarp = wid >> 1;
    int b0 = blockIdx.x * 2;
    if (tid < ZP_WORDS) ZP[tid] = 0;

    const __nv_bfloat16* inb = in + (size_t)b0 * 225 * 32;
    for (int i = tid; i < 1800; i += 256) {
        int img = i / 900, rem = i % 900, px = rem >> 2, seg = rem & 3;
        cp16(rawb + (uint32_t)((img * 225 + px) * 40 + seg * 8) * 2,
             inb + (size_t)(img * 225 + px) * 32 + seg * 8);
    }
    auto issueB = [&](int j) {
        int oc = tid >> 2, seg = tid & 3;
        cp16(bsb + (uint32_t)((j % 3) * 64 * 40 + oc * 40 + seg * 8) * 2,
             wt + ((size_t)j * 64 + oc) * 32 + seg * 8);
    };
    issueB(0); CP_COMMIT();
    issueB(1); CP_COMMIT();

    int tile_r = lane & 15, khalf = lane >> 4;
    int aimg[4], aoh[4], aow[4];
    #pragma unroll
    for (int mt = 0; mt < 4; mt++) {
        int r = mwarp * 64 + mt * 16 + tile_r;
        aimg[mt] = r >> 6; int px = r & 63; aoh[mt] = px >> 3; aow[mt] = px & 7;
    }
    int nB = nwarp * 16 + (lane & 7);
    int khB = (lane >> 3) & 1;

    float acc[4][2][4];
    #pragma unroll
    for (int mt = 0; mt < 4; mt++)
        #pragma unroll
        for (int nt = 0; nt < 2; nt++)
            #pragma unroll
            for (int q = 0; q < 4; q++) acc[mt][nt][q] = 0.f;

    for (int i = 0; i < 9; i++) {
        CP_WAIT1();
        __syncthreads();
        if (i + 2 < 9) { issueB(i + 2); }
        CP_COMMIT();
        int kh = i / 3, kw = i % 3;
        uint32_t aaddr[4];
        #pragma unroll
        for (int mt = 0; mt < 4; mt++) {
            int ih = 2 * aoh[mt] - 1 + kh, iw = 2 * aow[mt] - 1 + kw;
            bool ok = ((unsigned)ih < 15u) && ((unsigned)iw < 15u);
            aaddr[mt] = ok ? rawb + (uint32_t)(((aimg[mt] * 225 + ih * 15 + iw) * 40 + khalf * 8) * 2) : zaddr;
        }
        uint32_t bbase = bsb + (uint32_t)((i % 3) * 64 * 40 * 2);
        #pragma unroll
        for (int kk = 0; kk < 2; kk++) {
            uint32_t a[4][4];
            #pragma unroll
            for (int mt = 0; mt < 4; mt++) ldsm_x4(a[mt], aaddr[mt] + kk * 32);
            uint32_t b[2][2];
            #pragma unroll
            for (int nt = 0; nt < 2; nt++)
                ldsm_x2(b[nt], bbase + (uint32_t)(((nB + nt * 8) * 40 + kk * 16 + khB * 8) * 2));
            #pragma unroll
            for (int mt = 0; mt < 4; mt++)
                #pragma unroll
                for (int nt = 0; nt < 2; nt++)
                    mma16(acc[mt][nt], a[mt], b[nt]);
        }
    }
    #pragma unroll
    for (int mt = 0; mt < 4; mt++)
        #pragma unroll
        for (int nt = 0; nt < 2; nt++) {
            int n = nwarp * 16 + nt * 8 + (lane & 3) * 2;
            float bv0 = bias[n], bv1 = bias[n + 1];
            #pragma unroll
            for (int h = 0; h < 2; h++) {
                int r = mwarp * 64 + mt * 16 + (lane >> 2) + h * 8;
                int img = r >> 6, px = r & 63;
                uint32_t pk = packbf(fmaxf(acc[mt][nt][h * 2 + 0] + bv0, 0.f),
                                     fmaxf(acc[mt][nt][h * 2 + 1] + bv1, 0.f));
                *(uint32_t*)(out + ((size_t)(b0 + img) * 64 + px) * 64 + n) = pk;
            }
        }
}

// ================= bf16 mma implicit-GEMM conv 3x3 s1 p1 (NHWC), N-sliced =================
template <int CIN, int COUTF, int NSPL>
__global__ __launch_bounds__(256, 2) void conv_mma(const __nv_bfloat16* __restrict__ in,
                                                   const __nv_bfloat16* __restrict__ wt,
                                                   const float* __restrict__ bias,
                                                   __nv_bfloat16* __restrict__ out) {
    constexpr int CINP = CIN + 8;
    constexpr int CB = CIN / 32, NCH = 9 * CB;
    constexpr int COUT = COUTF / NSPL;
    constexpr int NW = COUT / 4, NT = NW / 8;
    extern __shared__ char dynsm[];
    __nv_bfloat16* RAW = (__nv_bfloat16*)dynsm;       // 128 * CINP
    __nv_bfloat16* BS = RAW + 128 * CINP;             // 3 * COUT * 40
    uint32_t* ZP = (uint32_t*)(BS + 3 * COUT * 40);   // 64B zero pad
    uint32_t rawb = smem_u32(RAW), bsb = smem_u32(BS), zaddr = smem_u32(ZP);
    int tid = threadIdx.x, lane = tid & 31, wid = tid >> 5;
    int mwarp = wid & 1, nwarp = wid >> 1;
    int b0 = blockIdx.x * 2;
    int sl = (NSPL > 1) ? blockIdx.y : 0;
    if (tid < ZP_WORDS) ZP[tid] = 0;

    const __nv_bfloat16* inb = in + (size_t)b0 * 64 * CIN;
    constexpr int SEGS = CIN / 8;
    #pragma unroll
    for (int u = 0; u < 128 * SEGS / 256; u++) {
        int i = u * 256 + tid;
        int px = i / SEGS, seg = i % SEGS;
        cp16(rawb + (uint32_t)(px * CINP + seg * 8) * 2, inb + (size_t)px * CIN + seg * 8);
    }
    auto issueB = [&](int j) {
        int cb = j % CB, t = j / CB;
        const __nv_bfloat16* wb = wt + ((size_t)t * COUTF + sl * COUT) * CIN + cb * 32;
        uint32_t dst = bsb + (uint32_t)((j % 3) * COUT * 40) * 2;
        #pragma unroll
        for (int u = 0; u < COUT * 4 / 256; u++) {
            int i = u * 256 + tid;
            int oc = i >> 2, seg = i & 3;
            cp16(dst + (uint32_t)(oc * 40 + seg * 8) * 2, wb + (size_t)oc * CIN + seg * 8);
        }
    };
    issueB(0); CP_COMMIT();
    issueB(1); CP_COMMIT();

    int tile_r = lane & 15, khalf = lane >> 4;
    int aimg[4], aoh[4], aow[4];
    #pragma unroll
    for (int mt = 0; mt < 4; mt++) {
        int r = mwarp * 64 + mt * 16 + tile_r;
        aimg[mt] = r >> 6; int px = r & 63; aoh[mt] = px >> 3; aow[mt] = px & 7;
    }
    int nB = nwarp * NW + (lane & 7);
    int khB = (lane >> 3) & 1;

    float acc[4][NT][4];
    #pragma unroll
    for (int mt = 0; mt < 4; mt++)
        #pragma unroll
        for (int nt = 0; nt < NT; nt++)
            #pragma unroll
            for (int q = 0; q < 4; q++) acc[mt][nt][q] = 0.f;

    for (int i = 0; i < NCH; i++) {
        CP_WAIT1();
        __syncthreads();
        if (i + 2 < NCH) { issueB(i + 2); }
        CP_COMMIT();
        int cb = i % CB, t = i / CB, kh = t / 3, kw = t % 3;
        uint32_t aaddr[4];
        #pragma unroll
        for (int mt = 0; mt < 4; mt++) {
            int ih = aoh[mt] + kh - 1, iw = aow[mt] + kw - 1;
            bool ok = ((unsigned)ih < 8u) && ((unsigned)iw < 8u);
            aaddr[mt] = ok ? rawb + (uint32_t)(((((aimg[mt] << 6) + (ih << 3) + iw) * CINP) + cb * 32 + khalf * 8) * 2)
                           : zaddr;
        }
        uint32_t bbase = bsb + (uint32_t)((i % 3) * COUT * 40 * 2);
        #pragma unroll
        for (int kk = 0; kk < 2; kk++) {
            uint32_t a[4][4];
            #pragma unroll
            for (int mt = 0; mt < 4; mt++) ldsm_x4(a[mt], aaddr[mt] + kk * 32);
            uint32_t b[NT][2];
            #pragma unroll
            for (int nt = 0; nt < NT; nt++)
                ldsm_x2(b[nt], bbase + (uint32_t)(((nB + nt * 8) * 40 + kk * 16 + khB * 8) * 2));
            #pragma unroll
            for (int mt = 0; mt < 4; mt++)
                #pragma unroll
                for (int nt = 0; nt < NT; nt++)
                    mma16(acc[mt][nt], a[mt], b[nt]);
        }
    }
    #pragma unroll
    for (int mt = 0; mt < 4; mt++)
        #pragma unroll
        for (int nt = 0; nt < NT; nt++) {
            int n = nwarp * NW + nt * 8 + (lane & 3) * 2;
            float bv0 = bias[sl * COUT + n], bv1 = bias[sl * COUT + n + 1];
            #pragma unroll
            for (int h = 0; h < 2; h++) {
                int r = mwarp * 64 + mt * 16 + (lane >> 2) + h * 8;
                int img = r >> 6, px = r & 63;
                uint32_t pk = packbf(fmaxf(acc[mt][nt][h * 2 + 0] + bv0, 0.f),
                                     fmaxf(acc[mt][nt][h * 2 + 1] + bv1, 0.f));
                *(uint32_t*)(out + ((size_t)(b0 + img) * 64 + px) * COUTF + sl * COUT + n) = pk;
            }
        }
}

// ================= bf16 mma GEMM: z0 = h4 @ encwT^T, M64 N64 K-chunk 64 =================
__global__ __launch_bounds__(256, 2) void enc_mma(const __nv_bfloat16* __restrict__ A,
                                                  const __nv_bfloat16* __restrict__ Bw,
                                                  const float* __restrict__ bias,
                                                  float* __restrict__ C) {
    constexpr int K = 16384, NCH = K / 64;
    extern __shared__ char dynsm[];
    __nv_bfloat16* AS = (__nv_bfloat16*)dynsm;        // 3 * 64*72
    __nv_bfloat16* BSm = AS + 3 * 64 * 72;            // 3 * 64*72
    uint32_t asb = smem_u32(AS), bsb = smem_u32(BSm);
    int tid = threadIdx.x, lane = tid & 31, wid = tid >> 5;
    int mwarp = wid & 1, nwarp = wid >> 1;
    int m0 = blockIdx.x * 64, n0 = blockIdx.y * 64;

    auto issue = [&](int j) {
        int buf = j % 3;
        const __nv_bfloat16* Ab = A + (size_t)m0 * K + j * 64;
        const __nv_bfloat16* Bb = Bw + (size_t)n0 * K + j * 64;
        #pragma unroll
        for (int u = 0; u < 2; u++) {
            int i = u * 256 + tid;
            int r = i >> 3, seg = i & 7;
            cp16(asb + (uint32_t)(buf * 64 * 72 + r * 72 + seg * 8) * 2, Ab + (size_t)r * K + seg * 8);
        }
        #pragma unroll
        for (int u = 0; u < 2; u++) {
            int i = u * 256 + tid;
            int r = i >> 3, seg = i & 7;
            cp16(bsb + (uint32_t)(buf * 64 * 72 + r * 72 + seg * 8) * 2, Bb + (size_t)r * K + seg * 8);
        }
    };
    issue(0); CP_COMMIT();
    issue(1); CP_COMMIT();

    int tile_r = lane & 15, khalf = lane >> 4;
    int ra[2];
    #pragma unroll
    for (int mt = 0; mt < 2; mt++) ra[mt] = mwarp * 32 + mt * 16 + tile_r;
    int nB = nwarp * 16 + (lane & 7);
    int khB = (lane >> 3) & 1;

    float acc[2][2][4];
    #pragma unroll
    for (int mt = 0; mt < 2; mt++)
        #pragma unroll
        for (int nt = 0; nt < 2; nt++)
            #pragma unroll
            for (int q = 0; q < 4; q++) acc[mt][nt][q] = 0.f;

    for (int i = 0; i < NCH; i++) {
        CP_WAIT1();
        __syncthreads();
        if (i + 2 < NCH) { issue(i + 2); }
        CP_COMMIT();
        uint32_t abase = asb + (uint32_t)((i % 3) * 64 * 72 * 2);
        uint32_t bbase = bsb + (uint32_t)((i % 3) * 64 * 72 * 2);
        #pragma unroll
        for (int kk = 0; kk < 4; kk++) {
            uint32_t a[2][4];
            #pragma unroll
            for (int mt = 0; mt < 2; mt++)
                ldsm_x4(a[mt], abase + (uint32_t)((ra[mt] * 72 + kk * 16 + khalf * 8) * 2));
            uint32_t b[2][2];
            #pragma unroll
            for (int nt = 0; nt < 2; nt++)
                ldsm_x2(b[nt], bbase + (uint32_t)(((nB + nt * 8) * 72 + kk * 16 + khB * 8) * 2));
            #pragma unroll
            for (int mt = 0; mt < 2; mt++)
                #pragma unroll
                for (int nt = 0; nt < 2; nt++)
                    mma16(acc[mt][nt], a[mt], b[nt]);
        }
    }
    #pragma unroll
    for (int mt = 0; mt < 2; mt++)
        #pragma unroll
        for (int nt = 0; nt < 2; nt++) {
            int n = n0 + nwarp * 16 + nt * 8 + (lane & 3) * 2;
            float bv0 = bias[n], bv1 = bias[n + 1];
            #pragma unroll
            for (int h = 0; h < 2; h++) {
                int m = m0 + mwarp * 32 + mt * 16 + (lane >> 2) + h * 8;
                float2 o;
                o.x = acc[mt][nt][h * 2 + 0] + bv0;
                o.y = acc[mt][nt][h * 2 + 1] + bv1;
                *(float2*)(C + (size_t)m * 256 + n) = o;
            }
        }
}

// ================= fp32 GEMM (node_fc only) =================
__global__ void gemm_kernel(const float* __restrict__ A, const float* __restrict__ Bm,
                            const float* __restrict__ bias, float* __restrict__ C,
                            int K, int N) {
    __shared__ float As[8][68];
    __shared__ float Bs[8][68];
    int tid = threadIdx.x;
    int row0 = blockIdx.x * 64;
    int col0 = blockIdx.y * 64;
    int tr = tid / 16, tc = tid % 16;
    int ar = tid / 8, ac = tid % 8;
    int br = tid / 64, bc = tid % 64;
    float acc[4][4];
    #pragma unroll
    for (int i = 0; i < 4; i++)
        #pragma unroll
        for (int j = 0; j < 4; j++) acc[i][j] = 0.f;
    for (int k0 = 0; k0 < K; k0 += 8) {
        #pragma unroll
        for (int i = 0; i < 2; i++)
            As[ac][ar + i * 32] = A[(size_t)(row0 + ar + i * 32) * K + k0 + ac];
        #pragma unroll
        for (int i = 0; i < 2; i++)
            Bs[br + i * 4][bc] = Bm[(size_t)(k0 + br + i * 4) * N + col0 + bc];
        __syncthreads();
        #pragma unroll
        for (int kk = 0; kk < 8; kk++) {
            float4 a = *(const float4*)&As[kk][tr * 4];
            float4 b = *(const float4*)&Bs[kk][tc * 4];
            acc[0][0] += a.x * b.x; acc[0][1] += a.x * b.y; acc[0][2] += a.x * b.z; acc[0][3] += a.x * b.w;
            acc[1][0] += a.y * b.x; acc[1][1] += a.y * b.y; acc[1][2] += a.y * b.z; acc[1][3] += a.y * b.w;
            acc[2][0] += a.z * b.x; acc[2][1] += a.z * b.y; acc[2][2] += a.z * b.z; acc[2][3] += a.z * b.w;
            acc[3][0] += a.w * b.x; acc[3][1] += a.w * b.y; acc[3][2] += a.w * b.z; acc[3][3] += a.w * b.w;
        }
        __syncthreads();
    }
    #pragma unroll
    for (int i = 0; i < 4; i++) {
        int r = row0 + tr * 4 + i;
        #pragma unroll
        for (int j = 0; j < 4; j++) {
            int cidx = col0 + tc * 4 + j;
            C[(size_t)r * N + cidx] = acc[i][j] + bias[cidx];
        }
    }
}

// ================= proto distances + softmax/gate + blend =================
__global__ void proto_kernel(const float* __restrict__ protos,
                             const float* __restrict__ temp_raw,
                             const float* __restrict__ gate) {
    __shared__ float zs[8 * 256];
    __shared__ float dsm[8 * 256];
    __shared__ float wsm[8 * 256];
    __shared__ float zn2[8];
    int b0 = blockIdx.x * 8;
    int tid = threadIdx.x;
    for (int i = tid; i < 2048; i += 256) zs[i] = g_z[(size_t)b0 * 256 + i];
    __syncthreads();
    if (tid < 8) {
        float s = 0.f;
        for (int k = 0; k < 256; k++) { float v = zs[tid * 256 + k]; s += v * v; }
        zn2[tid] = s;
    }
    __syncthreads();
    int j = tid;
    float ap[8], ag[8];
    #pragma unroll
    for (int r = 0; r < 8; r++) { ap[r] = 0.f; ag[r] = 0.f; }
    for (int k = 0; k < 256; k++) {
        float pv = g_protosT[k * 256 + j];
        float gv = g_gridT[k * 256 + j];
        #pragma unroll
        for (int r = 0; r < 8; r++) {
            float zv = zs[r * 256 + k];
            ap[r] += zv * pv;
            ag[r] += zv * gv;
        }
    }
    float pj = g_pn2[j], gj = g_gn2[j];
    #pragma unroll
    for (int r = 0; r < 8; r++) {
        float d1 = sqrtf(fmaxf(zn2[r] + pj - 2.f * ap[r], 0.f));
        float d2 = sqrtf(fmaxf(zn2[r] + gj - 2.f * ag[r], 0.f));
        dsm[r * 256 + j] = d1 + d2;
    }
    __syncthreads();
    float temp = 1.f / (1.f + expf(-temp_raw[0])) * 0.999f + 0.001f;
    float invt = 1.f / temp;
    int wr = tid >> 5;
    int lane = tid & 31;
    float mn = dsm[wr * 256 + lane];
    #pragma unroll
    for (int t = 1; t < 8; t++) mn = fminf(mn, dsm[wr * 256 + lane + t * 32]);
    #pragma unroll
    for (int o = 16; o; o >>= 1) mn = fminf(mn, __shfl_xor_sync(0xffffffffu, mn, o));
    float pvals[8];
    float S = 0.f;
    #pragma unroll
    for (int t = 0; t < 8; t++) {
        float e = expf((mn - dsm[wr * 256 + lane + t * 32]) * invt);
        pvals[t] = e; S += e;
    }
    #pragma unroll
    for (int o = 16; o; o >>= 1) S += __shfl_xor_sync(0xffffffffu, S, o);
    float invS = 1.f / S;
    float T = 0.f;
    #pragma unroll
    for (int t = 0; t < 8; t++) {
        int jj = lane + t * 32;
        float sg = 1.f / (1.f + expf(-gate[jj]));
        float bb = pvals[t] * invS * sg;
        pvals[t] = bb; T += bb;
    }
    #pragma unroll
    for (int o = 16; o; o >>= 1) T += __shfl_xor_sync(0xffffffffu, T, o);
    float inv = 1.f / (T + 1e-8f);
    #pragma unroll
    for (int t = 0; t < 8; t++) wsm[wr * 256 + lane + t * 32] = pvals[t] * inv;
    __syncthreads();
    int d = tid;
    float accb[8];
    #pragma unroll
    for (int r = 0; r < 8; r++) accb[r] = 0.f;
    for (int jj = 0; jj < 256; jj++) {
        float pv = protos[(size_t)jj * 256 + d];
        #pragma unroll
        for (int r = 0; r < 8; r++) accb[r] += wsm[r * 256 + jj] * pv;
    }
    #pragma unroll
    for (int r = 0; r < 8; r++) g_blend[(size_t)(b0 + r) * 256 + d] = accb[r];
}

__global__ void logits_kernel(const float* __restrict__ clf_b, float* __restrict__ out) {
    __shared__ float bs[32 * 256];
    __shared__ float ws[2560];
    int b0 = blockIdx.x * 32;
    int tid = threadIdx.x;  // 320
    for (int i = tid; i < 8192; i += 320) bs[i] = g_blend[(size_t)b0 * 256 + i];
    for (int i = tid; i < 2560; i += 320) ws[i] = g_wsum[i];
    __syncthreads();
    int r = tid / 10, c = tid % 10;
    float acc = clf_b[c];
    for (int d = 0; d < 256; d++) acc += bs[r * 256 + d] * ws[d * 10 + c];
    out[(size_t)(b0 + r) * 10 + c] = acc;
}

// ================= launch =================
extern "C" void kernel_launch(void* const* d_in, const int* in_sizes, int n_in,
                              void* d_out, int out_size) {
    const float* x        = (const float*)d_in[0];
    const float* conv1_w  = (const float*)d_in[2];
    const float* conv1_b  = (const float*)d_in[3];
    const float* conv2_w  = (const float*)d_in[4];
    const float* conv2_b  = (const float*)d_in[5];
    const float* conv3_w  = (const float*)d_in[6];
    const float* conv3_b  = (const float*)d_in[7];
    const float* conv4_w  = (const float*)d_in[8];
    const float* conv4_b  = (const float*)d_in[9];
    const float* enc_w    = (const float*)d_in[10];
    const float* enc_b    = (const float*)d_in[11];
    const float* clf_w    = (const float*)d_in[18];
    const float* clf_b    = (const float*)d_in[19];
    const float* node_fc_w = (const float*)d_in[20];
    const float* node_fc_b = (const float*)d_in[21];
    const float* protos   = (const float*)d_in[22];
    const float* grid_pos = (const float*)d_in[23];
    const float* temp_raw = (const float*)d_in[24];
    const float* gate     = (const float*)d_in[25];
    float* out = (float*)d_out;

    __nv_bfloat16 *p_h1, *p_h2, *p_h3, *p_h4, *p_encwT, *p_w2t, *p_w3t, *p_w4t;
    float *p_z0, *p_z;
    cudaGetSymbolAddress((void**)&p_h1, g_h1bf);
    cudaGetSymbolAddress((void**)&p_h2, g_h2bf);
    cudaGetSymbolAddress((void**)&p_h3, g_h3bf);
    cudaGetSymbolAddress((void**)&p_h4, g_h4bf);
    cudaGetSymbolAddress((void**)&p_z0, g_z0);
    cudaGetSymbolAddress((void**)&p_z, g_z);
    cudaGetSymbolAddress((void**)&p_encwT, g_encwT);
    cudaGetSymbolAddress((void**)&p_w2t, g_w2t);
    cudaGetSymbolAddress((void**)&p_w3t, g_w3t);
    cudaGetSymbolAddress((void**)&p_w4t, g_w4t);

    // dynamic smem (bytes); +64 for the zero pad
    static const int SM2 = (2 * 225 * 40 + 3 * 64 * 40) * 2 + 64;            // 51424
    static const int SM3 = (128 * 72 + 3 * 128 * 40) * 2 + 64;               // 49216
    static const int SM4 = (128 * 136 + 3 * 128 * 40) * 2 + 64;              // 65600
    static const int SME = 3 * 2 * 64 * 72 * 2;                              // 55296
    cudaFuncSetAttribute(conv2_mma, cudaFuncAttributeMaxDynamicSharedMemorySize, SM2);
    cudaFuncSetAttribute(conv_mma<64, 128, 1>, cudaFuncAttributeMaxDynamicSharedMemorySize, SM3);
    cudaFuncSetAttribute(conv_mma<128, 256, 2>, cudaFuncAttributeMaxDynamicSharedMemorySize, SM4);
    cudaFuncSetAttribute(enc_mma, cudaFuncAttributeMaxDynamicSharedMemorySize, SME);

    conv1_kernel<<<B_, 256>>>(x, conv1_w, conv1_b);
    prep_all<<<2281, 256>>>(protos, grid_pos, clf_w, enc_w, conv2_w, conv3_w, conv4_w);

    conv2_mma<<<B_ / 2, 256, SM2>>>(p_h1, p_w2t, conv2_b, p_h2);
    conv_mma<64, 128, 1><<<dim3(B_ / 2, 1), 256, SM3>>>(p_h2, p_w3t, conv3_b, p_h3);
    conv_mma<128, 256, 2><<<dim3(B_ / 2, 2), 256, SM4>>>(p_h3, p_w4t, conv4_b, p_h4);

    enc_mma<<<dim3(64, 4), 256, SME>>>(p_h4, p_encwT, enc_b, p_z0);
    gemm_kernel<<<dim3(64, 4), 256>>>(p_z0, node_fc_w, node_fc_b, p_z, D_, D_);

    proto_kernel<<<B_ / 8, 256>>>(protos, temp_raw, gate);
    logits_kernel<<<B_ / 32, 320>>>(clf_b, out);
}

// round 11
// speedup vs baseline: 8.0099x; 1.0279x over previous
#include <cuda_runtime.h>
#include <cuda_bf16.h>
#include <math.h>
#include <cstdint>

#define B_ 4096
#define D_ 256
#define NPROTO 256

// ---------------- scratch (device globals; no allocations allowed) ----------------
__device__ __nv_bfloat16 g_h1bf[(size_t)B_ * 225 * 32];   // NHWC bf16
__device__ __nv_bfloat16 g_h2bf[(size_t)B_ * 64 * 64];    // NHWC bf16
__device__ __nv_bfloat16 g_h3bf[(size_t)B_ * 64 * 128];   // NHWC bf16
__device__ __nv_bfloat16 g_h4bf[(size_t)B_ * 64 * 256];   // NHWC bf16
__device__ float g_z0[B_ * D_];
__device__ float g_z[B_ * D_];
__device__ float g_blend[B_ * D_];
__device__ float g_protosT[NPROTO * D_];
__device__ float g_gridT[NPROTO * D_];
__device__ float g_pn2[NPROTO];
__device__ float g_gn2[NPROTO];
__device__ float g_wsum[D_ * 10];
__device__ __nv_bfloat16 g_encwT[(size_t)D_ * 16384];   // [d][k], k = p*256+c
__device__ __nv_bfloat16 g_w2t[9 * 64 * 32];            // [tap][oc][c]
__device__ __nv_bfloat16 g_w3t[9 * 128 * 64];
__device__ __nv_bfloat16 g_w4t[9 * 256 * 128];

// ================= helpers =================
__device__ __forceinline__ uint32_t smem_u32(const void* p) {
    uint32_t a;
    asm("{ .reg .u64 t; cvta.to.shared.u64 t, %1; cvt.u32.u64 %0, t; }" : "=r"(a) : "l"(p));
    return a;
}
__device__ __forceinline__ void cp16(uint32_t s, const void* g) {
    asm volatile("cp.async.cg.shared.global [%0], [%1], 16;" :: "r"(s), "l"(g));
}
#define CP_COMMIT() asm volatile("cp.async.commit_group;" ::: "memory")
#define CP_WAIT1()  asm volatile("cp.async.wait_group 1;" ::: "memory")
#define CP_WAIT0()  asm volatile("cp.async.wait_group 0;" ::: "memory")

__device__ __forceinline__ uint32_t packbf(float lo, float hi) {
    uint32_t r; asm("cvt.rn.bf16x2.f32 %0, %1, %2;" : "=r"(r) : "f"(hi), "f"(lo)); return r;
}
__device__ __forceinline__ void mma16(float c[4], const uint32_t a[4], const uint32_t b[2]) {
    asm volatile(
        "mma.sync.aligned.m16n8k16.row.col.f32.bf16.bf16.f32 "
        "{%0,%1,%2,%3}, {%4,%5,%6,%7}, {%8,%9}, {%0,%1,%2,%3};"
        : "+f"(c[0]), "+f"(c[1]), "+f"(c[2]), "+f"(c[3])
        : "r"(a[0]), "r"(a[1]), "r"(a[2]), "r"(a[3]), "r"(b[0]), "r"(b[1]));
}
__device__ __forceinline__ void ldsm_x4(uint32_t r[4], uint32_t addr) {
    asm volatile("ldmatrix.sync.aligned.m8n8.x4.shared.b16 {%0,%1,%2,%3}, [%4];"
        : "=r"(r[0]), "=r"(r[1]), "=r"(r[2]), "=r"(r[3]) : "r"(addr));
}
__device__ __forceinline__ void ldsm_x2(uint32_t r[2], uint32_t addr) {
    asm volatile("ldmatrix.sync.aligned.m8n8.x2.shared.b16 {%0,%1}, [%2];"
        : "=r"(r[0]), "=r"(r[1]) : "r"(addr));
}

// ================= merged prep kernel =================
__global__ void prep_all(const float* __restrict__ protos,
                         const float* __restrict__ grid_pos,
                         const float* __restrict__ clf_w,
                         const float* __restrict__ enc_w,
                         const float* __restrict__ w2,
                         const float* __restrict__ w3,
                         const float* __restrict__ w4) {
    __shared__ float sbuf[32 * 257];
    int bid = blockIdx.x;
    int tid = threadIdx.x;
    if (bid < 256) {
        float pv = protos[bid * D_ + tid];
        float gv = grid_pos[bid * D_ + tid];
        g_protosT[tid * NPROTO + bid] = pv;
        g_gridT[tid * NPROTO + bid] = gv;
        float* red = sbuf;
        red[tid] = pv * pv;
        __syncthreads();
        for (int s = 128; s > 0; s >>= 1) { if (tid < s) red[tid] += red[tid + s]; __syncthreads(); }
        if (tid == 0) g_pn2[bid] = red[0];
        __syncthreads();
        red[tid] = gv * gv;
        __syncthreads();
        for (int s = 128; s > 0; s >>= 1) { if (tid < s) red[tid] += red[tid + s]; __syncthreads(); }
        if (tid == 0) g_gn2[bid] = red[0];
    } else if (bid == 256) {
        for (int i = tid; i < D_ * 10; i += 256) {
            int dd = i / 10, c = i % 10;
            float s = 0.f;
            #pragma unroll
            for (int h = 0; h < 4; h++) s += clf_w[(h * 256 + dd) * 10 + c];
            g_wsum[i] = s;
        }
    } else if (bid < 769) {
        float (*s)[257] = (float (*)[257])sbuf;
        int k0 = (bid - 257) * 32;
        for (int r = 0; r < 32; r++) {
            int k = k0 + r;
            int c = k & 255, p = k >> 8;
            s[r][tid] = enc_w[(size_t)(c * 64 + p) * 256 + tid];
        }
        __syncthreads();
        int lane = tid & 31, w = tid >> 5;
        for (int d = w; d < 256; d += 8)
            g_encwT[(size_t)d * 16384 + k0 + lane] = __float2bfloat16(s[lane][d]);
    } else {
        const float* w; __nv_bfloat16* wt; int COUT, CIN, base;
        if (bid < 841)       { w = w2; wt = g_w2t; COUT = 64;  CIN = 32;  base = 769; }
        else if (bid < 1129) { w = w3; wt = g_w3t; COUT = 128; CIN = 64;  base = 841; }
        else                 { w = w4; wt = g_w4t; COUT = 256; CIN = 128; base = 1129; }
        int i = (bid - base) * 256 + tid;
        if (i < 9 * COUT * CIN) {
            int c = i % CIN;
            int oc = (i / CIN) % COUT;
            int t = i / (CIN * COUT);
            wt[i] = __float2bfloat16(w[((size_t)(oc * CIN + c)) * 9 + t]);
        }
    }
}

// ================= conv1: 3->32, 5x5, s2, p1 — branch-free padded, reg weights =================
__global__ __launch_bounds__(256) void conv1_kernel(const float* __restrict__ x,
                                                    const float* __restrict__ w,
                                                    const float* __restrict__ bias) {
    __shared__ __align__(16) float xs[3 * 34 * 36];
    __shared__ float ws[2400];
    int b = blockIdx.x, tid = threadIdx.x;
    for (int i = tid; i < 3 * 34 * 36; i += 256) xs[i] = 0.f;
    for (int i = tid; i < 2400; i += 256) ws[i] = w[i];
    __syncthreads();
    const float* xb = x + (size_t)b * 3072;
    for (int i = tid; i < 3072; i += 256) {
        int c = i >> 10, rem = i & 1023, ih = rem >> 5, iw = rem & 31;
        xs[c * 1224 + (ih + 1) * 36 + (iw + 1)] = xb[i];
    }
    __syncthreads();
    int oc = tid & 31, wg = tid >> 5;
    float wr[75];
    #pragma unroll
    for (int t = 0; t < 75; t++) wr[t] = ws[oc * 75 + t];
    float bv = bias[oc];
    __nv_bfloat16* ob = g_h1bf + (size_t)b * 225 * 32 + oc;
    for (int oh = wg; oh < 15; oh += 8) {
        float acc[8];
        #pragma unroll
        for (int j = 0; j < 8; j++) acc[j] = bv;
        #pragma unroll
        for (int c = 0; c < 3; c++)
            #pragma unroll
            for (int kh = 0; kh < 5; kh++) {
                const float* row = xs + c * 1224 + (2 * oh + kh) * 36;
                float xv[20];
                #pragma unroll
                for (int q = 0; q < 5; q++) *(float4*)(xv + q * 4) = *(const float4*)(row + q * 4);
                #pragma unroll
                for (int kw = 0; kw < 5; kw++) {
                    float wv = wr[c * 25 + kh * 5 + kw];
                    #pragma unroll
                    for (int ow = 0; ow < 8; ow++) acc[ow] += xv[2 * ow + kw] * wv;
                }
            }
        #pragma unroll
        for (int ow = 0; ow < 8; ow++)
            ob[(size_t)(oh * 15 + ow) * 32] = __float2bfloat16(fmaxf(acc[ow], 0.f));
        float acc2[7];
        #pragma unroll
        for (int j = 0; j < 7; j++) acc2[j] = bv;
        #pragma unroll
        for (int c = 0; c < 3; c++)
            #pragma unroll
            for (int kh = 0; kh < 5; kh++) {
                const float* row = xs + c * 1224 + (2 * oh + kh) * 36 + 16;
                float xv[20];
                #pragma unroll
                for (int q = 0; q < 5; q++) *(float4*)(xv + q * 4) = *(const float4*)(row + q * 4);
                #pragma unroll
                for (int kw = 0; kw < 5; kw++) {
                    float wv = wr[c * 25 + kh * 5 + kw];
                    #pragma unroll
                    for (int j = 0; j < 7; j++) acc2[j] += xv[2 * j + kw] * wv;
                }
            }
        #pragma unroll
        for (int j = 0; j < 7; j++)
            ob[(size_t)(oh * 15 + 8 + j) * 32] = __float2bfloat16(fmaxf(acc2[j], 0.f));
    }
}

// ================= conv2 mma: 32->64, 3x3, s2, p1 — spatially padded 17x17 RAW =================
__global__ __launch_bounds__(256, 2) void conv2_mma(const __nv_bfloat16* __restrict__ in,
                                                    const __nv_bfloat16* __restrict__ wt,
                                                    const float* __restrict__ bias,
                                                    __nv_bfloat16* __restrict__ out) {
    // RAW: [img][py 0..16][px 0..16][40]; image interior at (+1,+1)
    extern __shared__ char dynsm[];
    __nv_bfloat16* RAW = (__nv_bfloat16*)dynsm;            // 2*289*40 = 23120 bf16
    __nv_bfloat16* BS = RAW + 2 * 289 * 40;                // 3*64*40
    uint32_t rawb = smem_u32(RAW), bsb = smem_u32(BS);
    int tid = threadIdx.x, lane = tid & 31, wid = tid >> 5;
    int mwarp = wid & 1, nwarp = wid >> 1;
    int b0 = blockIdx.x * 2;

    // zero whole padded RAW (46240 B = 2890 uint4)
    uint4 z4 = make_uint4(0, 0, 0, 0);
    for (int i = tid; i < 2890; i += 256) ((uint4*)RAW)[i] = z4;
    __syncthreads();

    const __nv_bfloat16* inb = in + (size_t)b0 * 225 * 32;
    for (int i = tid; i < 1800; i += 256) {
        int img = i / 900, rem = i % 900, px = rem >> 2, seg = rem & 3;
        int ih = px / 15, iw = px % 15;
        int pad = img * 289 + (ih + 1) * 17 + (iw + 1);
        cp16(rawb + (uint32_t)((pad * 40 + seg * 8) * 2),
             inb + (size_t)(img * 225 + px) * 32 + seg * 8);
    }
    auto issueB = [&](int j) {
        int oc = tid >> 2, seg = tid & 3;
        cp16(bsb + (uint32_t)((j % 3) * 64 * 40 + oc * 40 + seg * 8) * 2,
             wt + ((size_t)j * 64 + oc) * 32 + seg * 8);
    };
    issueB(0); CP_COMMIT();
    issueB(1); CP_COMMIT();

    int tile_r = lane & 15, khalf = lane >> 4;
    uint32_t abase[4];
    #pragma unroll
    for (int mt = 0; mt < 4; mt++) {
        int r = mwarp * 64 + mt * 16 + tile_r;
        int img = r >> 6, px = r & 63, oh = px >> 3, ow = px & 7;
        // padded coords at tap (0,0): (2*oh, 2*ow)
        int pad = img * 289 + (2 * oh) * 17 + (2 * ow);
        abase[mt] = rawb + (uint32_t)((pad * 40 + khalf * 8) * 2);
    }
    int nB = nwarp * 16 + (lane & 7);
    int khB = (lane >> 3) & 1;

    float acc[4][2][4];
    #pragma unroll
    for (int mt = 0; mt < 4; mt++)
        #pragma unroll
        for (int nt = 0; nt < 2; nt++)
            #pragma unroll
            for (int q = 0; q < 4; q++) acc[mt][nt][q] = 0.f;

    for (int i = 0; i < 9; i++) {
        CP_WAIT1();
        __syncthreads();
        if (i + 2 < 9) { issueB(i + 2); }
        CP_COMMIT();
        int kh = i / 3, kw = i % 3;
        uint32_t toff = (uint32_t)(((kh * 17 + kw) * 40) * 2);
        uint32_t aaddr[4];
        #pragma unroll
        for (int mt = 0; mt < 4; mt++) aaddr[mt] = abase[mt] + toff;
        uint32_t bbase = bsb + (uint32_t)((i % 3) * 64 * 40 * 2);
        #pragma unroll
        for (int kk = 0; kk < 2; kk++) {
            uint32_t a[4][4];
            #pragma unroll
            for (int mt = 0; mt < 4; mt++) ldsm_x4(a[mt], aaddr[mt] + kk * 32);
            uint32_t b[2][2];
            #pragma unroll
            for (int nt = 0; nt < 2; nt++)
                ldsm_x2(b[nt], bbase + (uint32_t)(((nB + nt * 8) * 40 + kk * 16 + khB * 8) * 2));
            #pragma unroll
            for (int mt = 0; mt < 4; mt++)
                #pragma unroll
                for (int nt = 0; nt < 2; nt++)
                    mma16(acc[mt][nt], a[mt], b[nt]);
        }
    }
    #pragma unroll
    for (int mt = 0; mt < 4; mt++)
        #pragma unroll
        for (int nt = 0; nt < 2; nt++) {
            int n = nwarp * 16 + nt * 8 + (lane & 3) * 2;
            float bv0 = bias[n], bv1 = bias[n + 1];
            #pragma unroll
            for (int h = 0; h < 2; h++) {
                int r = mwarp * 64 + mt * 16 + (lane >> 2) + h * 8;
                int img = r >> 6, px = r & 63;
                uint32_t pk = packbf(fmaxf(acc[mt][nt][h * 2 + 0] + bv0, 0.f),
                                     fmaxf(acc[mt][nt][h * 2 + 1] + bv1, 0.f));
                *(uint32_t*)(out + ((size_t)(b0 + img) * 64 + px) * 64 + n) = pk;
            }
        }
}

// ================= bf16 mma implicit-GEMM conv 3x3 s1 p1 — padded 10x10 RAW, 2-chunk stages ======
// RING: cp.async ring depth (3 for conv3, 2 for conv4 to fit 2 CTAs/SM)
template <int CIN, int COUTF, int NSPL, int RING>
__global__ __launch_bounds__(256, 2) void conv_mma(const __nv_bfloat16* __restrict__ in,
                                                   const __nv_bfloat16* __restrict__ wt,
                                                   const float* __restrict__ bias,
                                                   __nv_bfloat16* __restrict__ out) {
    constexpr int CINP = CIN + 8;
    constexpr int CB = CIN / 32, NCH = 9 * CB, ND = NCH / 2;
    constexpr int COUT = COUTF / NSPL;
    constexpr int NW = COUT / 4, NT = NW / 8;
    constexpr int RAWQ = 200 * CINP * 2 / 16;      // uint4 count of padded RAW
    extern __shared__ char dynsm[];
    __nv_bfloat16* RAW = (__nv_bfloat16*)dynsm;       // 2 imgs * 100 padded px * CINP
    __nv_bfloat16* BS = RAW + 200 * CINP;             // RING * COUT * 80
    uint32_t rawb = smem_u32(RAW), bsb = smem_u32(BS);
    int tid = threadIdx.x, lane = tid & 31, wid = tid >> 5;
    int mwarp = wid & 1, nwarp = wid >> 1;
    int b0 = blockIdx.x * 2;
    int sl = (NSPL > 1) ? blockIdx.y : 0;

    uint4 z4 = make_uint4(0, 0, 0, 0);
    for (int i = tid; i < RAWQ; i += 256) ((uint4*)RAW)[i] = z4;
    __syncthreads();

    const __nv_bfloat16* inb = in + (size_t)b0 * 64 * CIN;
    constexpr int SEGS = CIN / 8;
    #pragma unroll
    for (int u = 0; u < 128 * SEGS / 256; u++) {
        int i = u * 256 + tid;
        int px = i / SEGS, seg = i % SEGS;
        int img = px >> 6, p = px & 63, oh = p >> 3, ow = p & 7;
        int pad = img * 100 + (oh + 1) * 10 + (ow + 1);
        cp16(rawb + (uint32_t)((pad * CINP + seg * 8) * 2), inb + (size_t)px * CIN + seg * 8);
    }
    // stage i holds chunks 2i, 2i+1 (same tap)
    auto issueB2 = [&](int i) {
        int t = (2 * i) / CB;
        #pragma unroll
        for (int j = 0; j < 2; j++) {
            int cb = (2 * i + j) % CB;
            const __nv_bfloat16* wb = wt + ((size_t)t * COUTF + sl * COUT) * CIN + cb * 32;
            uint32_t dst = bsb + (uint32_t)(((i % RING) * COUT * 80 + j * COUT * 40) * 2);
            #pragma unroll
            for (int u = 0; u < COUT * 4 / 256; u++) {
                int idx = u * 256 + tid;
                int oc = idx >> 2, seg = idx & 3;
                cp16(dst + (uint32_t)((oc * 40 + seg * 8) * 2), wb + (size_t)oc * CIN + seg * 8);
            }
        }
    };
    issueB2(0); CP_COMMIT();
    if (RING == 3) { issueB2(1); CP_COMMIT(); }

    int tile_r = lane & 15, khalf = lane >> 4;
    uint32_t abase[4];
    #pragma unroll
    for (int mt = 0; mt < 4; mt++) {
        int r = mwarp * 64 + mt * 16 + tile_r;
        int img = r >> 6, px = r & 63, oh = px >> 3, ow = px & 7;
        int pad = img * 100 + (oh + 1) * 10 + (ow + 1);
        abase[mt] = rawb + (uint32_t)((pad * CINP + khalf * 8) * 2);
    }
    int nB = nwarp * NW + (lane & 7);
    int khB = (lane >> 3) & 1;

    float acc[4][NT][4];
    #pragma unroll
    for (int mt = 0; mt < 4; mt++)
        #pragma unroll
        for (int nt = 0; nt < NT; nt++)
            #pragma unroll
            for (int q = 0; q < 4; q++) acc[mt][nt][q] = 0.f;

    for (int i = 0; i < ND; i++) {
        if (RING == 3) { CP_WAIT1(); } else { CP_WAIT0(); }
        __syncthreads();
        if (i + RING - 1 < ND) { issueB2(i + RING - 1); }
        CP_COMMIT();
        int t = (2 * i) / CB;
        int kh = t / 3, kw = t % 3;
        int toff = ((kh - 1) * 10 + (kw - 1)) * CINP * 2;
        #pragma unroll
        for (int j = 0; j < 2; j++) {
            int cb = (2 * i + j) % CB;
            uint32_t aaddr[4];
            #pragma unroll
            for (int mt = 0; mt < 4; mt++)
                aaddr[mt] = (uint32_t)((int)abase[mt] + toff + cb * 64);
            uint32_t bbase = bsb + (uint32_t)(((i % RING) * COUT * 80 + j * COUT * 40) * 2);
            #pragma unroll
            for (int kk = 0; kk < 2; kk++) {
                uint32_t a[4][4];
                #pragma unroll
                for (int mt = 0; mt < 4; mt++) ldsm_x4(a[mt], aaddr[mt] + kk * 32);
                uint32_t b[NT][2];
                #pragma unroll
                for (int nt = 0; nt < NT; nt++)
                    ldsm_x2(b[nt], bbase + (uint32_t)(((nB + nt * 8) * 40 + kk * 16 + khB * 8) * 2));
                #pragma unroll
                for (int mt = 0; mt < 4; mt++)
                    #pragma unroll
                    for (int nt = 0; nt < NT; nt++)
                        mma16(acc[mt][nt], a[mt], b[nt]);
            }
        }
    }
    #pragma unroll
    for (int mt = 0; mt < 4; mt++)
        #pragma unroll
        for (int nt = 0; nt < NT; nt++) {
            int n = nwarp * NW + nt * 8 + (lane & 3) * 2;
            float bv0 = bias[sl * COUT + n], bv1 = bias[sl * COUT + n + 1];
            #pragma unroll
            for (int h = 0; h < 2; h++) {
                int r = mwarp * 64 + mt * 16 + (lane >> 2) + h * 8;
                int img = r >> 6, px = r & 63;
                uint32_t pk = packbf(fmaxf(acc[mt][nt][h * 2 + 0] + bv0, 0.f),
                                     fmaxf(acc[mt][nt][h * 2 + 1] + bv1, 0.f));
                *(uint32_t*)(out + ((size_t)(b0 + img) * 64 + px) * COUTF + sl * COUT + n) = pk;
            }
        }
}

// ================= bf16 mma GEMM: z0 = h4 @ encwT^T, M64 N64 K-chunk 64 =================
__global__ __launch_bounds__(256, 2) void enc_mma(const __nv_bfloat16* __restrict__ A,
                                                  const __nv_bfloat16* __restrict__ Bw,
                                                  const float* __restrict__ bias,
                                                  float* __restrict__ C) {
    constexpr int K = 16384, NCH = K / 64;
    extern __shared__ char dynsm[];
    __nv_bfloat16* AS = (__nv_bfloat16*)dynsm;        // 3 * 64*72
    __nv_bfloat16* BSm = AS + 3 * 64 * 72;            // 3 * 64*72
    uint32_t asb = smem_u32(AS), bsb = smem_u32(BSm);
    int tid = threadIdx.x, lane = tid & 31, wid = tid >> 5;
    int mwarp = wid & 1, nwarp = wid >> 1;
    int m0 = blockIdx.x * 64, n0 = blockIdx.y * 64;

    auto issue = [&](int j) {
        int buf = j % 3;
        const __nv_bfloat16* Ab = A + (size_t)m0 * K + j * 64;
        const __nv_bfloat16* Bb = Bw + (size_t)n0 * K + j * 64;
        #pragma unroll
        for (int u = 0; u < 2; u++) {
            int i = u * 256 + tid;
            int r = i >> 3, seg = i & 7;
            cp16(asb + (uint32_t)(buf * 64 * 72 + r * 72 + seg * 8) * 2, Ab + (size_t)r * K + seg * 8);
        }
        #pragma unroll
        for (int u = 0; u < 2; u++) {
            int i = u * 256 + tid;
            int r = i >> 3, seg = i & 7;
            cp16(bsb + (uint32_t)(buf * 64 * 72 + r * 72 + seg * 8) * 2, Bb + (size_t)r * K + seg * 8);
        }
    };
    issue(0); CP_COMMIT();
    issue(1); CP_COMMIT();

    int tile_r = lane & 15, khalf = lane >> 4;
    int ra[2];
    #pragma unroll
    for (int mt = 0; mt < 2; mt++) ra[mt] = mwarp * 32 + mt * 16 + tile_r;
    int nB = nwarp * 16 + (lane & 7);
    int khB = (lane >> 3) & 1;

    float acc[2][2][4];
    #pragma unroll
    for (int mt = 0; mt < 2; mt++)
        #pragma unroll
        for (int nt = 0; nt < 2; nt++)
            #pragma unroll
            for (int q = 0; q < 4; q++) acc[mt][nt][q] = 0.f;

    for (int i = 0; i < NCH; i++) {
        CP_WAIT1();
        __syncthreads();
        if (i + 2 < NCH) { issue(i + 2); }
        CP_COMMIT();
        uint32_t abase = asb + (uint32_t)((i % 3) * 64 * 72 * 2);
        uint32_t bbase = bsb + (uint32_t)((i % 3) * 64 * 72 * 2);
        #pragma unroll
        for (int kk = 0; kk < 4; kk++) {
            uint32_t a[2][4];
            #pragma unroll
            for (int mt = 0; mt < 2; mt++)
                ldsm_x4(a[mt], abase + (uint32_t)((ra[mt] * 72 + kk * 16 + khalf * 8) * 2));
            uint32_t b[2][2];
            #pragma unroll
            for (int nt = 0; nt < 2; nt++)
                ldsm_x2(b[nt], bbase + (uint32_t)(((nB + nt * 8) * 72 + kk * 16 + khB * 8) * 2));
            #pragma unroll
            for (int mt = 0; mt < 2; mt++)
                #pragma unroll
                for (int nt = 0; nt < 2; nt++)
                    mma16(acc[mt][nt], a[mt], b[nt]);
        }
    }
    #pragma unroll
    for (int mt = 0; mt < 2; mt++)
        #pragma unroll
        for (int nt = 0; nt < 2; nt++) {
            int n = n0 + nwarp * 16 + nt * 8 + (lane & 3) * 2;
            float bv0 = bias[n], bv1 = bias[n + 1];
            #pragma unroll
            for (int h = 0; h < 2; h++) {
                int m = m0 + mwarp * 32 + mt * 16 + (lane >> 2) + h * 8;
                float2 o;
                o.x = acc[mt][nt][h * 2 + 0] + bv0;
                o.y = acc[mt][nt][h * 2 + 1] + bv1;
                *(float2*)(C + (size_t)m * 256 + n) = o;
            }
        }
}

// ================= fp32 GEMM (node_fc only) =================
__global__ void gemm_kernel(const float* __restrict__ A, const float* __restrict__ Bm,
                            const float* __restrict__ bias, float* __restrict__ C,
                            int K, int N) {
    __shared__ float As[8][68];
    __shared__ float Bs[8][68];
    int tid = threadIdx.x;
    int row0 = blockIdx.x * 64;
    int col0 = blockIdx.y * 64;
    int tr = tid / 16, tc = tid % 16;
    int ar = tid / 8, ac = tid % 8;
    int br = tid / 64, bc = tid % 64;
    float acc[4][4];
    #pragma unroll
    for (int i = 0; i < 4; i++)
        #pragma unroll
        for (int j = 0; j < 4; j++) acc[i][j] = 0.f;
    for (int k0 = 0; k0 < K; k0 += 8) {
        #pragma unroll
        for (int i = 0; i < 2; i++)
            As[ac][ar + i * 32] = A[(size_t)(row0 + ar + i * 32) * K + k0 + ac];
        #pragma unroll
        for (int i = 0; i < 2; i++)
            Bs[br + i * 4][bc] = Bm[(size_t)(k0 + br + i * 4) * N + col0 + bc];
        __syncthreads();
        #pragma unroll
        for (int kk = 0; kk < 8; kk++) {
            float4 a = *(const float4*)&As[kk][tr * 4];
            float4 b = *(const float4*)&Bs[kk][tc * 4];
            acc[0][0] += a.x * b.x; acc[0][1] += a.x * b.y; acc[0][2] += a.x * b.z; acc[0][3] += a.x * b.w;
            acc[1][0] += a.y * b.x; acc[1][1] += a.y * b.y; acc[1][2] += a.y * b.z; acc[1][3] += a.y * b.w;
            acc[2][0] += a.z * b.x; acc[2][1] += a.z * b.y; acc[2][2] += a.z * b.z; acc[2][3] += a.z * b.w;
            acc[3][0] += a.w * b.x; acc[3][1] += a.w * b.y; acc[3][2] += a.w * b.z; acc[3][3] += a.w * b.w;
        }
        __syncthreads();
    }
    #pragma unroll
    for (int i = 0; i < 4; i++) {
        int r = row0 + tr * 4 + i;
        #pragma unroll
        for (int j = 0; j < 4; j++) {
            int cidx = col0 + tc * 4 + j;
            C[(size_t)r * N + cidx] = acc[i][j] + bias[cidx];
        }
    }
}

// ================= proto distances + softmax/gate + blend =================
__global__ void proto_kernel(const float* __restrict__ protos,
                             const float* __restrict__ temp_raw,
                             const float* __restrict__ gate) {
    __shared__ float zs[8 * 256];
    __shared__ float dsm[8 * 256];
    __shared__ float wsm[8 * 256];
    __shared__ float zn2[8];
    int b0 = blockIdx.x * 8;
    int tid = threadIdx.x;
    for (int i = tid; i < 2048; i += 256) zs[i] = g_z[(size_t)b0 * 256 + i];
    __syncthreads();
    if (tid < 8) {
        float s = 0.f;
        for (int k = 0; k < 256; k++) { float v = zs[tid * 256 + k]; s += v * v; }
        zn2[tid] = s;
    }
    __syncthreads();
    int j = tid;
    float ap[8], ag[8];
    #pragma unroll
    for (int r = 0; r < 8; r++) { ap[r] = 0.f; ag[r] = 0.f; }
    for (int k = 0; k < 256; k++) {
        float pv = g_protosT[k * 256 + j];
        float gv = g_gridT[k * 256 + j];
        #pragma unroll
        for (int r = 0; r < 8; r++) {
            float zv = zs[r * 256 + k];
            ap[r] += zv * pv;
            ag[r] += zv * gv;
        }
    }
    float pj = g_pn2[j], gj = g_gn2[j];
    #pragma unroll
    for (int r = 0; r < 8; r++) {
        float d1 = sqrtf(fmaxf(zn2[r] + pj - 2.f * ap[r], 0.f));
        float d2 = sqrtf(fmaxf(zn2[r] + gj - 2.f * ag[r], 0.f));
        dsm[r * 256 + j] = d1 + d2;
    }
    __syncthreads();
    float temp = 1.f / (1.f + expf(-temp_raw[0])) * 0.999f + 0.001f;
    float invt = 1.f / temp;
    int wr = tid >> 5;
    int lane = tid & 31;
    float mn = dsm[wr * 256 + lane];
    #pragma unroll
    for (int t = 1; t < 8; t++) mn = fminf(mn, dsm[wr * 256 + lane + t * 32]);
    #pragma unroll
    for (int o = 16; o; o >>= 1) mn = fminf(mn, __shfl_xor_sync(0xffffffffu, mn, o));
    float pvals[8];
    float S = 0.f;
    #pragma unroll
    for (int t = 0; t < 8; t++) {
        float e = expf((mn - dsm[wr * 256 + lane + t * 32]) * invt);
        pvals[t] = e; S += e;
    }
    #pragma unroll
    for (int o = 16; o; o >>= 1) S += __shfl_xor_sync(0xffffffffu, S, o);
    float invS = 1.f / S;
    float T = 0.f;
    #pragma unroll
    for (int t = 0; t < 8; t++) {
        int jj = lane + t * 32;
        float sg = 1.f / (1.f + expf(-gate[jj]));
        float bb = pvals[t] * invS * sg;
        pvals[t] = bb; T += bb;
    }
    #pragma unroll
    for (int o = 16; o; o >>= 1) T += __shfl_xor_sync(0xffffffffu, T, o);
    float inv = 1.f / (T + 1e-8f);
    #pragma unroll
    for (int t = 0; t < 8; t++) wsm[wr * 256 + lane + t * 32] = pvals[t] * inv;
    __syncthreads();
    int d = tid;
    float accb[8];
    #pragma unroll
    for (int r = 0; r < 8; r++) accb[r] = 0.f;
    for (int jj = 0; jj < 256; jj++) {
        float pv = protos[(size_t)jj * 256 + d];
        #pragma unroll
        for (int r = 0; r < 8; r++) accb[r] += wsm[r * 256 + jj] * pv;
    }
    #pragma unroll
    for (int r = 0; r < 8; r++) g_blend[(size_t)(b0 + r) * 256 + d] = accb[r];
}

__global__ void logits_kernel(const float* __restrict__ clf_b, float* __restrict__ out) {
    __shared__ float bs[32 * 256];
    __shared__ float ws[2560];
    int b0 = blockIdx.x * 32;
    int tid = threadIdx.x;  // 320
    for (int i = tid; i < 8192; i += 320) bs[i] = g_blend[(size_t)b0 * 256 + i];
    for (int i = tid; i < 2560; i += 320) ws[i] = g_wsum[i];
    __syncthreads();
    int r = tid / 10, c = tid % 10;
    float acc = clf_b[c];
    for (int d = 0; d < 256; d++) acc += bs[r * 256 + d] * ws[d * 10 + c];
    out[(size_t)(b0 + r) * 10 + c] = acc;
}

// ================= launch =================
extern "C" void kernel_launch(void* const* d_in, const int* in_sizes, int n_in,
                              void* d_out, int out_size) {
    const float* x        = (const float*)d_in[0];
    const float* conv1_w  = (const float*)d_in[2];
    const float* conv1_b  = (const float*)d_in[3];
    const float* conv2_w  = (const float*)d_in[4];
    const float* conv2_b  = (const float*)d_in[5];
    const float* conv3_w  = (const float*)d_in[6];
    const float* conv3_b  = (const float*)d_in[7];
    const float* conv4_w  = (const float*)d_in[8];
    const float* conv4_b  = (const float*)d_in[9];
    const float* enc_w    = (const float*)d_in[10];
    const float* enc_b    = (const float*)d_in[11];
    const float* clf_w    = (const float*)d_in[18];
    const float* clf_b    = (const float*)d_in[19];
    const float* node_fc_w = (const float*)d_in[20];
    const float* node_fc_b = (const float*)d_in[21];
    const float* protos   = (const float*)d_in[22];
    const float* grid_pos = (const float*)d_in[23];
    const float* temp_raw = (const float*)d_in[24];
    const float* gate     = (const float*)d_in[25];
    float* out = (float*)d_out;

    __nv_bfloat16 *p_h1, *p_h2, *p_h3, *p_h4, *p_encwT, *p_w2t, *p_w3t, *p_w4t;
    float *p_z0, *p_z;
    cudaGetSymbolAddress((void**)&p_h1, g_h1bf);
    cudaGetSymbolAddress((void**)&p_h2, g_h2bf);
    cudaGetSymbolAddress((void**)&p_h3, g_h3bf);
    cudaGetSymbolAddress((void**)&p_h4, g_h4bf);
    cudaGetSymbolAddress((void**)&p_z0, g_z0);
    cudaGetSymbolAddress((void**)&p_z, g_z);
    cudaGetSymbolAddress((void**)&p_encwT, g_encwT);
    cudaGetSymbolAddress((void**)&p_w2t, g_w2t);
    cudaGetSymbolAddress((void**)&p_w3t, g_w3t);
    cudaGetSymbolAddress((void**)&p_w4t, g_w4t);

    // dynamic smem (bytes)
    static const int SM2 = (2 * 289 * 40 + 3 * 64 * 40) * 2;                 // 61600
    static const int SM3 = (200 * 72 + 3 * 128 * 80) * 2;                    // 90240
    static const int SM4 = (200 * 136 + 2 * 128 * 80) * 2;                   // 95360
    static const int SME = 3 * 2 * 64 * 72 * 2;                              // 55296
    cudaFuncSetAttribute(conv2_mma, cudaFuncAttributeMaxDynamicSharedMemorySize, SM2);
    cudaFuncSetAttribute(conv_mma<64, 128, 1, 3>, cudaFuncAttributeMaxDynamicSharedMemorySize, SM3);
    cudaFuncSetAttribute(conv_mma<128, 256, 2, 2>, cudaFuncAttributeMaxDynamicSharedMemorySize, SM4);
    cudaFuncSetAttribute(enc_mma, cudaFuncAttributeMaxDynamicSharedMemorySize, SME);

    conv1_kernel<<<B_, 256>>>(x, conv1_w, conv1_b);
    prep_all<<<2281, 256>>>(protos, grid_pos, clf_w, enc_w, conv2_w, conv3_w, conv4_w);

    conv2_mma<<<B_ / 2, 256, SM2>>>(p_h1, p_w2t, conv2_b, p_h2);
    conv_mma<64, 128, 1, 3><<<dim3(B_ / 2, 1), 256, SM3>>>(p_h2, p_w3t, conv3_b, p_h3);
    conv_mma<128, 256, 2, 2><<<dim3(B_ / 2, 2), 256, SM4>>>(p_h3, p_w4t, conv4_b, p_h4);

    enc_mma<<<dim3(64, 4), 256, SME>>>(p_h4, p_encwT, enc_b, p_z0);
    gemm_kernel<<<dim3(64, 4), 256>>>(p_z0, node_fc_w, node_fc_b, p_z, D_, D_);

    proto_kernel<<<B_ / 8, 256>>>(protos, temp_raw, gate);
    logits_kernel<<<B_ / 32, 320>>>(clf_b, out);
}